// round 8
// baseline (speedup 1.0000x reference)
#include <cuda_runtime.h>
#include <cuda_bf16.h>
#include <math.h>
#include <stdint.h>

#define BT 8
#define NQ 1024
#define DM 512
#define HEADS 8
#define HD 64
#define TOT (BT*NQ*DM)

// fp32 scratch
__device__ float g_Qp[TOT];
__device__ float g_O [TOT];
__device__ float g_T [TOT];
__device__ float g_U [TOT];
// bf16 split scratch
__device__ __nv_bfloat16 g_Ah[TOT], g_Al[TOT];     // raw-Q splits, then T splits
__device__ __nv_bfloat16 g_Kbh[TOT], g_Kbl[TOT];   // raw-K splits
__device__ __nv_bfloat16 g_Qh[TOT], g_Ql[TOT];     // projected Q splits
__device__ __nv_bfloat16 g_Kh[TOT], g_Kl[TOT];     // projected K splits
__device__ __nv_bfloat16 g_Vh[TOT], g_Vl[TOT];     // projected V splits
__device__ __nv_bfloat16 g_Wth[4][DM*DM], g_Wtl[4][DM*DM]; // transposed weights

// ===========================================================================
// Helpers
// ===========================================================================
__device__ __forceinline__ uint32_t smem_u32(const void* p) {
    uint32_t a;
    asm("{ .reg .u64 t; cvta.to.shared.u64 t, %1; cvt.u32.u64 %0, t; }"
        : "=r"(a) : "l"(p));
    return a;
}

__device__ __forceinline__ void ldsm4(uint32_t r[4], uint32_t addr) {
    asm volatile("ldmatrix.sync.aligned.m8n8.x4.shared.b16 {%0,%1,%2,%3}, [%4];"
        : "=r"(r[0]), "=r"(r[1]), "=r"(r[2]), "=r"(r[3]) : "r"(addr));
}
__device__ __forceinline__ void ldsm4t(uint32_t r[4], uint32_t addr) {
    asm volatile("ldmatrix.sync.aligned.m8n8.x4.trans.shared.b16 {%0,%1,%2,%3}, [%4];"
        : "=r"(r[0]), "=r"(r[1]), "=r"(r[2]), "=r"(r[3]) : "r"(addr));
}

__device__ __forceinline__ void mma16816(float c[4], const uint32_t a[4],
                                         uint32_t b0, uint32_t b1) {
    asm volatile(
        "mma.sync.aligned.m16n8k16.row.col.f32.bf16.bf16.f32 "
        "{%0,%1,%2,%3}, {%4,%5,%6,%7}, {%8,%9}, {%0,%1,%2,%3};"
        : "+f"(c[0]), "+f"(c[1]), "+f"(c[2]), "+f"(c[3])
        : "r"(a[0]), "r"(a[1]), "r"(a[2]), "r"(a[3]), "r"(b0), "r"(b1));
}

__device__ __forceinline__ uint32_t packbf(float x, float y) {
    __nv_bfloat162 h = __floats2bfloat162_rn(x, y);
    return *reinterpret_cast<uint32_t*>(&h);
}

__device__ __forceinline__ void split_pair(float x, float y,
                                           uint32_t& hi, uint32_t& lo) {
    __nv_bfloat162 h = __floats2bfloat162_rn(x, y);
    float rx = x - __bfloat162float(h.x);
    float ry = y - __bfloat162float(h.y);
    hi = *reinterpret_cast<uint32_t*>(&h);
    lo = packbf(rx, ry);
}

__device__ __forceinline__ void cpa16(uint32_t dst, const void* src) {
    asm volatile("cp.async.ca.shared.global [%0], [%1], 16;"
                 :: "r"(dst), "l"(src));
}
#define CP_COMMIT() asm volatile("cp.async.commit_group;" ::: "memory")
#define CP_WAIT0()  asm volatile("cp.async.wait_group 0;" ::: "memory")
#define CP_WAIT1()  asm volatile("cp.async.wait_group 1;" ::: "memory")

// ===========================================================================
// Fused split-convert: two tensors fp32 -> bf16 hi/lo (blockIdx.y selects)
// ===========================================================================
__global__ __launch_bounds__(256) void cvt_split2(
    const float4* __restrict__ X0, __nv_bfloat16* __restrict__ X0h,
    __nv_bfloat16* __restrict__ X0l,
    const float4* __restrict__ X1, __nv_bfloat16* __restrict__ X1h,
    __nv_bfloat16* __restrict__ X1l, int n4)
{
    const float4* X = blockIdx.y ? X1 : X0;
    __nv_bfloat16* Xh = blockIdx.y ? X1h : X0h;
    __nv_bfloat16* Xl = blockIdx.y ? X1l : X0l;
    for (int i = blockIdx.x * blockDim.x + threadIdx.x; i < n4;
         i += gridDim.x * blockDim.x) {
        float4 v = X[i];
        uint32_t h0, l0, h1, l1;
        split_pair(v.x, v.y, h0, l0);
        split_pair(v.z, v.w, h1, l1);
        *(uint2*)&Xh[4 * i] = make_uint2(h0, h1);
        *(uint2*)&Xl[4 * i] = make_uint2(l0, l1);
    }
}

// Fused weight transpose + split for all 4 weights (blockIdx.z selects)
__global__ __launch_bounds__(256) void cvt_wt4(
    const float* __restrict__ W0, const float* __restrict__ W1,
    const float* __restrict__ W2, const float* __restrict__ W3,
    __nv_bfloat16* __restrict__ WthB, __nv_bfloat16* __restrict__ WtlB)
{
    const float* W = (blockIdx.z == 0) ? W0 : (blockIdx.z == 1) ? W1 :
                     (blockIdx.z == 2) ? W2 : W3;
    __nv_bfloat16* Wth = WthB + (size_t)blockIdx.z * DM * DM;
    __nv_bfloat16* Wtl = WtlB + (size_t)blockIdx.z * DM * DM;

    __shared__ float tile[32][33];
    const int tx = threadIdx.x, ty = threadIdx.y;  // 32 x 8
    const int kb = blockIdx.y * 32, nb = blockIdx.x * 32;
#pragma unroll
    for (int i = 0; i < 32; i += 8)
        tile[ty + i][tx] = W[(size_t)(kb + ty + i) * DM + nb + tx];
    __syncthreads();
#pragma unroll
    for (int i = 0; i < 32; i += 8) {
        float v = tile[tx][ty + i];
        __nv_bfloat16 h = __float2bfloat16(v);
        size_t o = (size_t)(nb + ty + i) * DM + kb + tx;
        Wth[o] = h;
        Wtl[o] = __float2bfloat16(v - __bfloat162float(h));
    }
}

// ===========================================================================
// mma.sync GEMM, cp.async 2-stage, single barrier per K-chunk.
// C[8192,512] = A @ W + bias  (MODE1: +relu+resid)
// CTA 128x128, 8 warps (warp tile 32x64), K-chunk 32.
// ===========================================================================
#define GLD 40                 // smem row stride (bf16)
#define GSTG (128 * GLD)       // elems per array per stage
#define G_SMEM (2 * 4 * GSTG * 2)   // bytes = 81920

template <int MODE, int WF32, int WSPL>
__global__ __launch_bounds__(256, 2) void gemm_mma(
    const __nv_bfloat16* __restrict__ Ah, const __nv_bfloat16* __restrict__ Al,
    const __nv_bfloat16* __restrict__ Bh, const __nv_bfloat16* __restrict__ Bl,
    const float* __restrict__ bias, const float* __restrict__ R,
    float* __restrict__ C, __nv_bfloat16* __restrict__ Ch,
    __nv_bfloat16* __restrict__ Cl)
{
    extern __shared__ __nv_bfloat16 gsm[];
    const uint32_t base = smem_u32(gsm);

    const int tid = threadIdx.x, wid = tid >> 5, lane = tid & 31;
    const int g = lane >> 2, t = lane & 3;
    const int lrow = lane & 15, lhalf = (lane >> 4) << 3;
    const int bm = blockIdx.y * 128, bn = blockIdx.x * 128;
    const int wm = (wid & 3) * 32, wn = (wid >> 2) * 64;

    // load mapping: 512 16B-chunks per array; 2 per thread
    const int cid0 = tid * 2;
    const int lr0 = cid0 >> 2, ls0 = (cid0 & 3) * 8;
    const int ls1 = ls0 + 8;

    float acc[2][8][4] = {};

    const uint32_t o0 = (uint32_t)(lr0 * GLD + ls0) * 2;
    const uint32_t o1 = (uint32_t)(lr0 * GLD + ls1) * 2;

    // prologue: issue chunk 0
    {
        uint32_t so = base;
        size_t ga0 = (size_t)(bm + lr0) * DM + ls0;
        size_t gb0 = (size_t)(bn + lr0) * DM + ls0;
        cpa16(so + o0, Ah + ga0);            cpa16(so + o1, Ah + ga0 + 8);
        cpa16(so + GSTG*2 + o0, Al + ga0);   cpa16(so + GSTG*2 + o1, Al + ga0 + 8);
        cpa16(so + 2*GSTG*2 + o0, Bh + gb0); cpa16(so + 2*GSTG*2 + o1, Bh + gb0 + 8);
        cpa16(so + 3*GSTG*2 + o0, Bl + gb0); cpa16(so + 3*GSTG*2 + o1, Bl + gb0 + 8);
        CP_COMMIT();
    }

    for (int c = 0; c < 16; ++c) {
        CP_WAIT0();
        __syncthreads();    // chunk c visible; all warps done with buf (c+1)&1
        if (c + 1 < 16) {
            const int k0 = (c + 1) * 32;
            uint32_t so = base + ((c + 1) & 1) * (4 * GSTG * 2);
            size_t ga0 = (size_t)(bm + lr0) * DM + k0 + ls0;
            size_t gb0 = (size_t)(bn + lr0) * DM + k0 + ls0;
            cpa16(so + o0, Ah + ga0);            cpa16(so + o1, Ah + ga0 + 8);
            cpa16(so + GSTG*2 + o0, Al + ga0);   cpa16(so + GSTG*2 + o1, Al + ga0 + 8);
            cpa16(so + 2*GSTG*2 + o0, Bh + gb0); cpa16(so + 2*GSTG*2 + o1, Bh + gb0 + 8);
            cpa16(so + 3*GSTG*2 + o0, Bl + gb0); cpa16(so + 3*GSTG*2 + o1, Bl + gb0 + 8);
            CP_COMMIT();
        }

        const uint32_t uS = base + (c & 1) * (4 * GSTG * 2);
        const uint32_t uAh = uS, uAl = uS + GSTG*2;
        const uint32_t uBh = uS + 2*GSTG*2, uBl = uS + 3*GSTG*2;

#pragma unroll
        for (int kb = 0; kb < 2; ++kb) {
            const uint32_t cofs = (uint32_t)(lhalf + kb * 16) * 2;
            uint32_t ah[2][4], al[2][4];
#pragma unroll
            for (int mf = 0; mf < 2; ++mf) {
                uint32_t rofs = (uint32_t)((wm + mf * 16 + lrow) * GLD) * 2 + cofs;
                ldsm4(ah[mf], uAh + rofs);
                ldsm4(al[mf], uAl + rofs);
            }
#pragma unroll
            for (int j = 0; j < 4; ++j) {
                uint32_t bhf[4], blf[4];
                uint32_t rofs = (uint32_t)((wn + j * 16 + lrow) * GLD) * 2 + cofs;
                ldsm4(bhf, uBh + rofs);
                ldsm4(blf, uBl + rofs);
#pragma unroll
                for (int mf = 0; mf < 2; ++mf) {
                    mma16816(acc[mf][2 * j],     ah[mf], bhf[0], bhf[2]);
                    mma16816(acc[mf][2 * j + 1], ah[mf], bhf[1], bhf[3]);
                    mma16816(acc[mf][2 * j],     ah[mf], blf[0], blf[2]);
                    mma16816(acc[mf][2 * j + 1], ah[mf], blf[1], blf[3]);
                    mma16816(acc[mf][2 * j],     al[mf], bhf[0], bhf[2]);
                    mma16816(acc[mf][2 * j + 1], al[mf], bhf[1], bhf[3]);
                }
            }
        }
    }

    // Epilogue
#pragma unroll
    for (int mf = 0; mf < 2; ++mf) {
#pragma unroll
        for (int nf = 0; nf < 8; ++nf) {
            const int row0 = bm + wm + mf * 16 + g;
            const int col = bn + wn + nf * 8 + 2 * t;
            float2 bv = *(const float2*)&bias[col];
            float v0 = acc[mf][nf][0] + bv.x, v1 = acc[mf][nf][1] + bv.y;
            float v2 = acc[mf][nf][2] + bv.x, v3 = acc[mf][nf][3] + bv.y;
            size_t q0 = (size_t)row0 * DM + col;
            size_t q1 = (size_t)(row0 + 8) * DM + col;
            if (MODE == 1) {
                float2 r0 = *(const float2*)&R[q0];
                float2 r1 = *(const float2*)&R[q1];
                v0 = r0.x + fmaxf(v0, 0.f); v1 = r0.y + fmaxf(v1, 0.f);
                v2 = r1.x + fmaxf(v2, 0.f); v3 = r1.y + fmaxf(v3, 0.f);
            }
            if (WF32) {
                *(float2*)&C[q0] = make_float2(v0, v1);
                *(float2*)&C[q1] = make_float2(v2, v3);
            }
            if (WSPL) {
                uint32_t h, l;
                split_pair(v0, v1, h, l);
                *(uint32_t*)&Ch[q0] = h; *(uint32_t*)&Cl[q0] = l;
                split_pair(v2, v3, h, l);
                *(uint32_t*)&Ch[q1] = h; *(uint32_t*)&Cl[q1] = l;
            }
        }
    }
}

// ===========================================================================
// Attention: CTA = 128 q-rows x (head, batch); 16 key-chunks of 64,
// cp.async 3-stage pipeline; Q fragments register-resident; one barrier/chunk.
// ===========================================================================
#define ATLD 72
#define ATILE (64 * ATLD)          // elems per 64-row tile
#define ASTG  (4 * ATILE)          // elems per stage (KH,KL,VH,VL)
#define A_SMEM (3 * ASTG * 2)      // 110592 bytes

__global__ __launch_bounds__(256, 2) void attn_mma(
    const float* __restrict__ Qp,
    const __nv_bfloat16* __restrict__ Qh, const __nv_bfloat16* __restrict__ Ql,
    const __nv_bfloat16* __restrict__ Kh, const __nv_bfloat16* __restrict__ Kl,
    const __nv_bfloat16* __restrict__ Vh, const __nv_bfloat16* __restrict__ Vl,
    float* __restrict__ O)
{
    extern __shared__ char sm[];
    const uint32_t sb = smem_u32(sm);
    const int tid = threadIdx.x, wid = tid >> 5, lane = tid & 31;
    const int g = lane >> 2, t = lane & 3;
    const int lrow = lane & 15, lhalf = (lane >> 4) << 3;
    const int b = blockIdx.z, h = blockIdx.y, q0 = blockIdx.x * 128;

    // ---- Q prologue: stage Q tile in smem, pull fragments to registers ----
    for (int idx = tid; idx < 1024; idx += 256) {
        int r = idx >> 3, s8 = (idx & 7) * 8;
        size_t go = ((size_t)(b * NQ) + q0 + r) * DM + h * HD + s8;
        int e = (r * ATLD + s8) * 2;
        *(uint4*)(sm + e) = *(const uint4*)&Qh[go];
        *(uint4*)(sm + 128 * ATLD * 2 + e) = *(const uint4*)&Ql[go];
    }
    __syncthreads();
    uint32_t aqh[4][4], aql[4][4];
#pragma unroll
    for (int kb = 0; kb < 4; ++kb) {
        uint32_t qro = (uint32_t)((wid * 16 + lrow) * ATLD) * 2 +
                       (uint32_t)(lhalf + kb * 16) * 2;
        ldsm4(aqh[kb], sb + qro);
        ldsm4(aql[kb], sb + 128 * ATLD * 2 + qro);
    }
    __syncthreads();   // Q reads done; smem reusable by pipeline

    // load mapping for a 64-row chunk: 512 16B-chunks per tile; 2 per thread
    const int cid0 = tid * 2;
    const int lr0 = cid0 >> 3, ls0 = (cid0 & 7) * 8;
    const int ls1 = ls0 + 8;
    const uint32_t o0 = (uint32_t)(lr0 * ATLD + ls0) * 2;
    const uint32_t o1 = (uint32_t)(lr0 * ATLD + ls1) * 2;

    float m0 = -1e30f, m1 = -1e30f, l0 = 0.f, l1 = 0.f;
    float oacc[8][4] = {};

    // prologue: issue chunks 0 and 1
#pragma unroll
    for (int pc = 0; pc < 2; ++pc) {
        uint32_t so = sb + pc * (ASTG * 2);
        size_t go = ((size_t)(b * NQ) + pc * 64 + lr0) * DM + h * HD + ls0;
        cpa16(so + o0, Kh + go);                cpa16(so + o1, Kh + go + 8);
        cpa16(so + ATILE*2 + o0, Kl + go);      cpa16(so + ATILE*2 + o1, Kl + go + 8);
        cpa16(so + 2*ATILE*2 + o0, Vh + go);    cpa16(so + 2*ATILE*2 + o1, Vh + go + 8);
        cpa16(so + 3*ATILE*2 + o0, Vl + go);    cpa16(so + 3*ATILE*2 + o1, Vl + go + 8);
        CP_COMMIT();
    }

    for (int kc = 0; kc < 16; ++kc) {
        if (kc < 15) CP_WAIT1(); else CP_WAIT0();
        __syncthreads();   // chunk kc visible; all warps done with buf (kc+2)%3
        if (kc + 2 < 16) {
            uint32_t so = sb + ((kc + 2) % 3) * (ASTG * 2);
            size_t go = ((size_t)(b * NQ) + (kc + 2) * 64 + lr0) * DM + h * HD + ls0;
            cpa16(so + o0, Kh + go);                cpa16(so + o1, Kh + go + 8);
            cpa16(so + ATILE*2 + o0, Kl + go);      cpa16(so + ATILE*2 + o1, Kl + go + 8);
            cpa16(so + 2*ATILE*2 + o0, Vh + go);    cpa16(so + 2*ATILE*2 + o1, Vh + go + 8);
            cpa16(so + 3*ATILE*2 + o0, Vl + go);    cpa16(so + 3*ATILE*2 + o1, Vl + go + 8);
            CP_COMMIT();
        }

        const uint32_t uS = sb + (kc % 3) * (ASTG * 2);
        const uint32_t uKH = uS, uKL = uS + ATILE*2;
        const uint32_t uVH = uS + 2*ATILE*2, uVL = uS + 3*ATILE*2;

        // ---- S = Q K^T (m16 x n64 x k64) ----
        float s[8][4];
#pragma unroll
        for (int nf = 0; nf < 8; ++nf)
#pragma unroll
            for (int e = 0; e < 4; ++e) s[nf][e] = 0.f;

#pragma unroll
        for (int kb = 0; kb < 4; ++kb) {
            const uint32_t cofs = (uint32_t)(lhalf + kb * 16) * 2;
#pragma unroll
            for (int j = 0; j < 4; ++j) {
                uint32_t bh[4], bl[4];
                uint32_t kro = (uint32_t)((j * 16 + lrow) * ATLD) * 2 + cofs;
                ldsm4(bh, uKH + kro);
                ldsm4(bl, uKL + kro);
                mma16816(s[2 * j],     aqh[kb], bh[0], bh[2]);
                mma16816(s[2 * j + 1], aqh[kb], bh[1], bh[3]);
                mma16816(s[2 * j],     aqh[kb], bl[0], bl[2]);
                mma16816(s[2 * j + 1], aqh[kb], bl[1], bl[3]);
                mma16816(s[2 * j],     aql[kb], bh[0], bh[2]);
                mma16816(s[2 * j + 1], aql[kb], bh[1], bh[3]);
            }
        }

        // ---- online softmax (rows g and g+8) ----
        const float scale = 0.125f;
        float rm0 = -1e30f, rm1 = -1e30f;
#pragma unroll
        for (int nf = 0; nf < 8; ++nf) {
            rm0 = fmaxf(rm0, fmaxf(s[nf][0], s[nf][1]));
            rm1 = fmaxf(rm1, fmaxf(s[nf][2], s[nf][3]));
        }
        rm0 = fmaxf(rm0, __shfl_xor_sync(0xffffffffu, rm0, 1));
        rm0 = fmaxf(rm0, __shfl_xor_sync(0xffffffffu, rm0, 2));
        rm1 = fmaxf(rm1, __shfl_xor_sync(0xffffffffu, rm1, 1));
        rm1 = fmaxf(rm1, __shfl_xor_sync(0xffffffffu, rm1, 2));
        float mn0 = fmaxf(m0, rm0 * scale);
        float mn1 = fmaxf(m1, rm1 * scale);
        float al0 = __expf(m0 - mn0);
        float al1 = __expf(m1 - mn1);
        float sum0 = 0.f, sum1 = 0.f;
#pragma unroll
        for (int nf = 0; nf < 8; ++nf) {
            s[nf][0] = __expf(fmaf(s[nf][0], scale, -mn0));
            s[nf][1] = __expf(fmaf(s[nf][1], scale, -mn0));
            s[nf][2] = __expf(fmaf(s[nf][2], scale, -mn1));
            s[nf][3] = __expf(fmaf(s[nf][3], scale, -mn1));
            sum0 += s[nf][0] + s[nf][1];
            sum1 += s[nf][2] + s[nf][3];
        }
        sum0 += __shfl_xor_sync(0xffffffffu, sum0, 1);
        sum0 += __shfl_xor_sync(0xffffffffu, sum0, 2);
        sum1 += __shfl_xor_sync(0xffffffffu, sum1, 1);
        sum1 += __shfl_xor_sync(0xffffffffu, sum1, 2);
        l0 = l0 * al0 + sum0;
        l1 = l1 * al1 + sum1;
        m0 = mn0; m1 = mn1;
#pragma unroll
        for (int nf = 0; nf < 8; ++nf) {
            oacc[nf][0] *= al0; oacc[nf][1] *= al0;
            oacc[nf][2] *= al1; oacc[nf][3] *= al1;
        }

        // ---- O += P V (m16 x n64 x k64), V frags via ldmatrix.trans ----
#pragma unroll
        for (int kb2 = 0; kb2 < 4; ++kb2) {
            uint32_t aph[4], apl[4];
            {
                const float* p0 = s[2 * kb2];
                const float* p1 = s[2 * kb2 + 1];
                split_pair(p0[0], p0[1], aph[0], apl[0]);
                split_pair(p0[2], p0[3], aph[1], apl[1]);
                split_pair(p1[0], p1[1], aph[2], apl[2]);
                split_pair(p1[2], p1[3], aph[3], apl[3]);
            }
#pragma unroll
            for (int j2 = 0; j2 < 4; ++j2) {
                uint32_t vh[4], vl[4];
                uint32_t vro = (uint32_t)(((kb2 * 16 + lrow) * ATLD) +
                                          j2 * 16 + lhalf) * 2;
                ldsm4t(vh, uVH + vro);
                ldsm4t(vl, uVL + vro);
                mma16816(oacc[2 * j2],     aph, vh[0], vh[1]);
                mma16816(oacc[2 * j2 + 1], aph, vh[2], vh[3]);
                mma16816(oacc[2 * j2],     aph, vl[0], vl[1]);
                mma16816(oacc[2 * j2 + 1], aph, vl[2], vl[3]);
                mma16816(oacc[2 * j2],     apl, vh[0], vh[1]);
                mma16816(oacc[2 * j2 + 1], apl, vh[2], vh[3]);
            }
        }
    }

    // ---- epilogue: normalize + Q residual ----
    const float inv0 = 1.f / l0, inv1 = 1.f / l1;
    const int r0 = q0 + wid * 16 + g;
#pragma unroll
    for (int nf = 0; nf < 8; ++nf) {
        const int d0 = nf * 8 + 2 * t;
        size_t oo0 = ((size_t)(b * NQ) + r0) * DM + h * HD + d0;
        size_t oo1 = oo0 + (size_t)8 * DM;
        float2 q0v = *(const float2*)&Qp[oo0];
        float2 q1v = *(const float2*)&Qp[oo1];
        *(float2*)&O[oo0] = make_float2(fmaf(oacc[nf][0], inv0, q0v.x),
                                        fmaf(oacc[nf][1], inv0, q0v.y));
        *(float2*)&O[oo1] = make_float2(fmaf(oacc[nf][2], inv1, q1v.x),
                                        fmaf(oacc[nf][3], inv1, q1v.y));
    }
}

// ===========================================================================
// LayerNorm (warp per row). EMIT=1 additionally writes bf16 hi/lo split.
// ===========================================================================
template <int EMIT>
__global__ __launch_bounds__(256) void ln_kernel(
    const float* __restrict__ X, const float* __restrict__ gam,
    const float* __restrict__ bet, float* __restrict__ Y,
    __nv_bfloat16* __restrict__ Yh, __nv_bfloat16* __restrict__ Yl)
{
    const int row = blockIdx.x * 8 + (threadIdx.x >> 5);
    const int lane = threadIdx.x & 31;
    const float* x = X + (size_t)row * DM;

    float v[16];
    float sum = 0.f, ss = 0.f;
#pragma unroll
    for (int i = 0; i < 4; ++i) {
        float4 tv = *(const float4*)(x + i * 128 + lane * 4);
        v[i * 4 + 0] = tv.x; v[i * 4 + 1] = tv.y;
        v[i * 4 + 2] = tv.z; v[i * 4 + 3] = tv.w;
        sum += tv.x + tv.y + tv.z + tv.w;
        ss += tv.x * tv.x + tv.y * tv.y + tv.z * tv.z + tv.w * tv.w;
    }
#pragma unroll
    for (int m = 16; m >= 1; m >>= 1) {
        sum += __shfl_xor_sync(0xffffffffu, sum, m);
        ss += __shfl_xor_sync(0xffffffffu, ss, m);
    }
    const float mean = sum * (1.f / DM);
    const float var = ss * (1.f / DM) - mean * mean;
    const float inv = rsqrtf(var + 1e-5f);

    float* y = Y + (size_t)row * DM;
#pragma unroll
    for (int i = 0; i < 4; ++i) {
        const int col = i * 128 + lane * 4;
        float4 gv = *(const float4*)(gam + col);
        float4 bb = *(const float4*)(bet + col);
        float4 o;
        o.x = (v[i * 4 + 0] - mean) * inv * gv.x + bb.x;
        o.y = (v[i * 4 + 1] - mean) * inv * gv.y + bb.y;
        o.z = (v[i * 4 + 2] - mean) * inv * gv.z + bb.z;
        o.w = (v[i * 4 + 3] - mean) * inv * gv.w + bb.w;
        *(float4*)(y + col) = o;
        if (EMIT) {
            uint32_t h0, l0, h1, l1;
            split_pair(o.x, o.y, h0, l0);
            split_pair(o.z, o.w, h1, l1);
            size_t e = (size_t)row * DM + col;
            *(uint2*)&Yh[e] = make_uint2(h0, h1);
            *(uint2*)&Yl[e] = make_uint2(l0, l1);
        }
    }
}

// ===========================================================================
extern "C" void kernel_launch(void* const* d_in, const int* in_sizes, int n_in,
                              void* d_out, int out_size)
{
    const float* Q  = (const float*)d_in[0];
    const float* K  = (const float*)d_in[1];
    const float* Wq = (const float*)d_in[2];
    const float* bq = (const float*)d_in[3];
    const float* Wk = (const float*)d_in[4];
    const float* bk = (const float*)d_in[5];
    const float* Wv = (const float*)d_in[6];
    const float* bv = (const float*)d_in[7];
    const float* Wo = (const float*)d_in[8];
    const float* bo = (const float*)d_in[9];
    const float* g0 = (const float*)d_in[10];
    const float* b0 = (const float*)d_in[11];
    const float* g1 = (const float*)d_in[12];
    const float* b1 = (const float*)d_in[13];
    float* out = (float*)d_out;

    float *Qp, *O, *T, *U;
    __nv_bfloat16 *Ah, *Al, *Kbh, *Kbl, *Qh, *Ql, *Kh, *Kl, *Vh, *Vl, *Wth, *Wtl;
    cudaGetSymbolAddress((void**)&Qp, g_Qp);
    cudaGetSymbolAddress((void**)&O,  g_O);
    cudaGetSymbolAddress((void**)&T,  g_T);
    cudaGetSymbolAddress((void**)&U,  g_U);
    cudaGetSymbolAddress((void**)&Ah, g_Ah);
    cudaGetSymbolAddress((void**)&Al, g_Al);
    cudaGetSymbolAddress((void**)&Kbh, g_Kbh);
    cudaGetSymbolAddress((void**)&Kbl, g_Kbl);
    cudaGetSymbolAddress((void**)&Qh, g_Qh);
    cudaGetSymbolAddress((void**)&Ql, g_Ql);
    cudaGetSymbolAddress((void**)&Kh, g_Kh);
    cudaGetSymbolAddress((void**)&Kl, g_Kl);
    cudaGetSymbolAddress((void**)&Vh, g_Vh);
    cudaGetSymbolAddress((void**)&Vl, g_Vl);
    cudaGetSymbolAddress((void**)&Wth, g_Wth);
    cudaGetSymbolAddress((void**)&Wtl, g_Wtl);

    static int attr_set = 0;
    if (!attr_set) {
        cudaFuncSetAttribute(attn_mma,
            cudaFuncAttributeMaxDynamicSharedMemorySize, A_SMEM);
        cudaFuncSetAttribute(gemm_mma<0,1,1>,
            cudaFuncAttributeMaxDynamicSharedMemorySize, G_SMEM);
        cudaFuncSetAttribute(gemm_mma<0,0,1>,
            cudaFuncAttributeMaxDynamicSharedMemorySize, G_SMEM);
        cudaFuncSetAttribute(gemm_mma<1,1,0>,
            cudaFuncAttributeMaxDynamicSharedMemorySize, G_SMEM);
        attr_set = 1;
    }

    const int WSZ = DM * DM;

    // #0: input splits (Q and K fused)
    cvt_split2<<<dim3(512, 2), 256>>>((const float4*)Q, Ah, Al,
                                      (const float4*)K, Kbh, Kbl, TOT / 4);
    // #1: all 4 weight transpose+splits fused
    cvt_wt4<<<dim3(16, 16, 4), dim3(32, 8)>>>(Wq, Wk, Wv, Wo, Wth, Wtl);

    dim3 gg(DM / 128, (BT * NQ) / 128);  // (4, 64)

    // #2-#4: projections (epilogues emit bf16 splits for attention)
    gemm_mma<0,1,1><<<gg, 256, G_SMEM>>>(Ah, Al, Wth + 0*WSZ, Wtl + 0*WSZ, bq,
                                         nullptr, Qp, Qh, Ql);
    gemm_mma<0,0,1><<<gg, 256, G_SMEM>>>(Kbh, Kbl, Wth + 1*WSZ, Wtl + 1*WSZ, bk,
                                         nullptr, nullptr, Kh, Kl);
    gemm_mma<0,0,1><<<gg, 256, G_SMEM>>>(Kbh, Kbl, Wth + 2*WSZ, Wtl + 2*WSZ, bv,
                                         nullptr, nullptr, Vh, Vl);

    // #5: attention + Q residual  (ncu -s 5 -c 1 captures THIS launch)
    attn_mma<<<dim3(NQ / 128, HEADS, BT), 256, A_SMEM>>>(Qp, Qh, Ql, Kh, Kl,
                                                         Vh, Vl, O);

    // #6: LN0 (emit bf16 split of T for the MLP GEMM)
    ln_kernel<1><<<(BT * NQ) / 8, 256>>>(O, g0, b0, T, Ah, Al);

    // #7: U = T + relu(T @ Wo + bo)
    gemm_mma<1,1,0><<<gg, 256, G_SMEM>>>(Ah, Al, Wth + 3*WSZ, Wtl + 3*WSZ, bo,
                                         T, U, nullptr, nullptr);

    // #8: LN1 -> out
    ln_kernel<0><<<(BT * NQ) / 8, 256>>>(U, g1, b1, out, nullptr, nullptr);
}

// round 9
// speedup vs baseline: 1.0140x; 1.0140x over previous
#include <cuda_runtime.h>
#include <cuda_bf16.h>
#include <math.h>
#include <stdint.h>

#define BT 8
#define NQ 1024
#define DM 512
#define HEADS 8
#define HD 64
#define TOT (BT*NQ*DM)

// fp32 scratch
__device__ float g_Qp[TOT];
__device__ float g_O [TOT];
__device__ float g_T [TOT];
__device__ float g_U [TOT];
// bf16 split scratch
__device__ __nv_bfloat16 g_Ah[TOT], g_Al[TOT];     // raw-Q splits, then T splits
__device__ __nv_bfloat16 g_Kbh[TOT], g_Kbl[TOT];   // raw-K splits
__device__ __nv_bfloat16 g_Qh[TOT], g_Ql[TOT];     // projected Q splits
__device__ __nv_bfloat16 g_Kh[TOT], g_Kl[TOT];     // projected K splits
__device__ __nv_bfloat16 g_Vh[TOT], g_Vl[TOT];     // projected V splits
__device__ __nv_bfloat16 g_Wth[4][DM*DM], g_Wtl[4][DM*DM]; // transposed weights

// ===========================================================================
// Helpers
// ===========================================================================
__device__ __forceinline__ uint32_t smem_u32(const void* p) {
    uint32_t a;
    asm("{ .reg .u64 t; cvta.to.shared.u64 t, %1; cvt.u32.u64 %0, t; }"
        : "=r"(a) : "l"(p));
    return a;
}

__device__ __forceinline__ void ldsm4(uint32_t r[4], uint32_t addr) {
    asm volatile("ldmatrix.sync.aligned.m8n8.x4.shared.b16 {%0,%1,%2,%3}, [%4];"
        : "=r"(r[0]), "=r"(r[1]), "=r"(r[2]), "=r"(r[3]) : "r"(addr));
}
__device__ __forceinline__ void ldsm4t(uint32_t r[4], uint32_t addr) {
    asm volatile("ldmatrix.sync.aligned.m8n8.x4.trans.shared.b16 {%0,%1,%2,%3}, [%4];"
        : "=r"(r[0]), "=r"(r[1]), "=r"(r[2]), "=r"(r[3]) : "r"(addr));
}

__device__ __forceinline__ void mma16816(float c[4], const uint32_t a[4],
                                         uint32_t b0, uint32_t b1) {
    asm volatile(
        "mma.sync.aligned.m16n8k16.row.col.f32.bf16.bf16.f32 "
        "{%0,%1,%2,%3}, {%4,%5,%6,%7}, {%8,%9}, {%0,%1,%2,%3};"
        : "+f"(c[0]), "+f"(c[1]), "+f"(c[2]), "+f"(c[3])
        : "r"(a[0]), "r"(a[1]), "r"(a[2]), "r"(a[3]), "r"(b0), "r"(b1));
}

__device__ __forceinline__ uint32_t packbf(float x, float y) {
    __nv_bfloat162 h = __floats2bfloat162_rn(x, y);
    return *reinterpret_cast<uint32_t*>(&h);
}

__device__ __forceinline__ void split_pair(float x, float y,
                                           uint32_t& hi, uint32_t& lo) {
    __nv_bfloat162 h = __floats2bfloat162_rn(x, y);
    float rx = x - __bfloat162float(h.x);
    float ry = y - __bfloat162float(h.y);
    hi = *reinterpret_cast<uint32_t*>(&h);
    lo = packbf(rx, ry);
}

__device__ __forceinline__ void cpa16(uint32_t dst, const void* src) {
    asm volatile("cp.async.ca.shared.global [%0], [%1], 16;"
                 :: "r"(dst), "l"(src));
}
#define CP_COMMIT() asm volatile("cp.async.commit_group;" ::: "memory")
#define CP_WAIT0()  asm volatile("cp.async.wait_group 0;" ::: "memory")
#define CP_WAIT1()  asm volatile("cp.async.wait_group 1;" ::: "memory")

// ===========================================================================
// Fused split-convert: two tensors fp32 -> bf16 hi/lo (blockIdx.y selects)
// ===========================================================================
__global__ __launch_bounds__(256) void cvt_split2(
    const float4* __restrict__ X0, __nv_bfloat16* __restrict__ X0h,
    __nv_bfloat16* __restrict__ X0l,
    const float4* __restrict__ X1, __nv_bfloat16* __restrict__ X1h,
    __nv_bfloat16* __restrict__ X1l, int n4)
{
    const float4* X = blockIdx.y ? X1 : X0;
    __nv_bfloat16* Xh = blockIdx.y ? X1h : X0h;
    __nv_bfloat16* Xl = blockIdx.y ? X1l : X0l;
    for (int i = blockIdx.x * blockDim.x + threadIdx.x; i < n4;
         i += gridDim.x * blockDim.x) {
        float4 v = X[i];
        uint32_t h0, l0, h1, l1;
        split_pair(v.x, v.y, h0, l0);
        split_pair(v.z, v.w, h1, l1);
        *(uint2*)&Xh[4 * i] = make_uint2(h0, h1);
        *(uint2*)&Xl[4 * i] = make_uint2(l0, l1);
    }
}

// Fused weight transpose + split for all 4 weights (blockIdx.z selects)
__global__ __launch_bounds__(256) void cvt_wt4(
    const float* __restrict__ W0, const float* __restrict__ W1,
    const float* __restrict__ W2, const float* __restrict__ W3,
    __nv_bfloat16* __restrict__ WthB, __nv_bfloat16* __restrict__ WtlB)
{
    const float* W = (blockIdx.z == 0) ? W0 : (blockIdx.z == 1) ? W1 :
                     (blockIdx.z == 2) ? W2 : W3;
    __nv_bfloat16* Wth = WthB + (size_t)blockIdx.z * DM * DM;
    __nv_bfloat16* Wtl = WtlB + (size_t)blockIdx.z * DM * DM;

    __shared__ float tile[32][33];
    const int tx = threadIdx.x, ty = threadIdx.y;  // 32 x 8
    const int kb = blockIdx.y * 32, nb = blockIdx.x * 32;
#pragma unroll
    for (int i = 0; i < 32; i += 8)
        tile[ty + i][tx] = W[(size_t)(kb + ty + i) * DM + nb + tx];
    __syncthreads();
#pragma unroll
    for (int i = 0; i < 32; i += 8) {
        float v = tile[tx][ty + i];
        __nv_bfloat16 h = __float2bfloat16(v);
        size_t o = (size_t)(nb + ty + i) * DM + kb + tx;
        Wth[o] = h;
        Wtl[o] = __float2bfloat16(v - __bfloat162float(h));
    }
}

// ===========================================================================
// GEMM mainloop body (shared by QKV-fused and MLP kernels).
// Term-major MMA ordering: same-accumulator spacing = 4 issues.
// ===========================================================================
#define GLD 40                 // smem row stride (bf16)
#define GSTG (128 * GLD)       // elems per array per stage
#define G_SMEM (2 * 4 * GSTG * 2)   // bytes = 81920

#define GEMM_MAINLOOP(Ahp, Alp, Bhp, Blp)                                     \
    {                                                                         \
        uint32_t so = base;                                                   \
        size_t ga0 = (size_t)(bm + lr0) * DM + ls0;                           \
        size_t gb0 = (size_t)(bn + lr0) * DM + ls0;                           \
        cpa16(so + o0, Ahp + ga0);            cpa16(so + o1, Ahp + ga0 + 8);  \
        cpa16(so + GSTG*2 + o0, Alp + ga0);   cpa16(so + GSTG*2 + o1, Alp + ga0 + 8); \
        cpa16(so + 2*GSTG*2 + o0, Bhp + gb0); cpa16(so + 2*GSTG*2 + o1, Bhp + gb0 + 8); \
        cpa16(so + 3*GSTG*2 + o0, Blp + gb0); cpa16(so + 3*GSTG*2 + o1, Blp + gb0 + 8); \
        CP_COMMIT();                                                          \
    }                                                                         \
    for (int c = 0; c < 16; ++c) {                                            \
        CP_WAIT0();                                                           \
        __syncthreads();                                                      \
        if (c + 1 < 16) {                                                     \
            const int k0 = (c + 1) * 32;                                      \
            uint32_t so = base + ((c + 1) & 1) * (4 * GSTG * 2);              \
            size_t ga0 = (size_t)(bm + lr0) * DM + k0 + ls0;                  \
            size_t gb0 = (size_t)(bn + lr0) * DM + k0 + ls0;                  \
            cpa16(so + o0, Ahp + ga0);            cpa16(so + o1, Ahp + ga0 + 8); \
            cpa16(so + GSTG*2 + o0, Alp + ga0);   cpa16(so + GSTG*2 + o1, Alp + ga0 + 8); \
            cpa16(so + 2*GSTG*2 + o0, Bhp + gb0); cpa16(so + 2*GSTG*2 + o1, Bhp + gb0 + 8); \
            cpa16(so + 3*GSTG*2 + o0, Blp + gb0); cpa16(so + 3*GSTG*2 + o1, Blp + gb0 + 8); \
            CP_COMMIT();                                                      \
        }                                                                     \
        const uint32_t uS = base + (c & 1) * (4 * GSTG * 2);                  \
        const uint32_t uAh = uS, uAl = uS + GSTG*2;                           \
        const uint32_t uBh = uS + 2*GSTG*2, uBl = uS + 3*GSTG*2;              \
        _Pragma("unroll")                                                     \
        for (int kb = 0; kb < 2; ++kb) {                                      \
            const uint32_t cofs = (uint32_t)(lhalf + kb * 16) * 2;            \
            uint32_t ah[2][4], al[2][4];                                      \
            _Pragma("unroll")                                                 \
            for (int mf = 0; mf < 2; ++mf) {                                  \
                uint32_t rofs = (uint32_t)((wm + mf * 16 + lrow) * GLD) * 2 + cofs; \
                ldsm4(ah[mf], uAh + rofs);                                    \
                ldsm4(al[mf], uAl + rofs);                                    \
            }                                                                 \
            _Pragma("unroll")                                                 \
            for (int j = 0; j < 4; ++j) {                                     \
                uint32_t bhf[4], blf[4];                                      \
                uint32_t rofs = (uint32_t)((wn + j * 16 + lrow) * GLD) * 2 + cofs; \
                ldsm4(bhf, uBh + rofs);                                       \
                ldsm4(blf, uBl + rofs);                                       \
                /* term hh (both m-frags) */                                  \
                mma16816(acc[0][2*j],   ah[0], bhf[0], bhf[2]);               \
                mma16816(acc[0][2*j+1], ah[0], bhf[1], bhf[3]);               \
                mma16816(acc[1][2*j],   ah[1], bhf[0], bhf[2]);               \
                mma16816(acc[1][2*j+1], ah[1], bhf[1], bhf[3]);               \
                /* term hl */                                                 \
                mma16816(acc[0][2*j],   ah[0], blf[0], blf[2]);               \
                mma16816(acc[0][2*j+1], ah[0], blf[1], blf[3]);               \
                mma16816(acc[1][2*j],   ah[1], blf[0], blf[2]);               \
                mma16816(acc[1][2*j+1], ah[1], blf[1], blf[3]);               \
                /* term lh */                                                 \
                mma16816(acc[0][2*j],   al[0], bhf[0], bhf[2]);               \
                mma16816(acc[0][2*j+1], al[0], bhf[1], bhf[3]);               \
                mma16816(acc[1][2*j],   al[1], bhf[0], bhf[2]);               \
                mma16816(acc[1][2*j+1], al[1], bhf[1], bhf[3]);               \
            }                                                                 \
        }                                                                     \
    }

// ===========================================================================
// Fused QKV projection GEMM: blockIdx.z selects (activation, weight, outputs)
//   z=0: Qp = Q @ Wq + bq   (fp32 + bf16 splits)
//   z=1: Kp = K @ Wk + bk   (bf16 splits only)
//   z=2: Vp = K @ Wv + bv   (bf16 splits only)
// ===========================================================================
__global__ __launch_bounds__(256, 2) void gemm_qkv(
    const __nv_bfloat16* __restrict__ QAh, const __nv_bfloat16* __restrict__ QAl,
    const __nv_bfloat16* __restrict__ KAh, const __nv_bfloat16* __restrict__ KAl,
    const __nv_bfloat16* __restrict__ WthB, const __nv_bfloat16* __restrict__ WtlB,
    const float* __restrict__ bq, const float* __restrict__ bk,
    const float* __restrict__ bv,
    float* __restrict__ Qp,
    __nv_bfloat16* __restrict__ Qh, __nv_bfloat16* __restrict__ Ql,
    __nv_bfloat16* __restrict__ Kh, __nv_bfloat16* __restrict__ Kl,
    __nv_bfloat16* __restrict__ Vh, __nv_bfloat16* __restrict__ Vl)
{
    extern __shared__ __nv_bfloat16 gsm[];
    const uint32_t base = smem_u32(gsm);

    const int z = blockIdx.z;
    const __nv_bfloat16* Ah = (z == 0) ? QAh : KAh;
    const __nv_bfloat16* Al = (z == 0) ? QAl : KAl;
    const __nv_bfloat16* Bh = WthB + (size_t)z * DM * DM;
    const __nv_bfloat16* Bl = WtlB + (size_t)z * DM * DM;
    const float* bias = (z == 0) ? bq : (z == 1) ? bk : bv;
    __nv_bfloat16* Ch = (z == 0) ? Qh : (z == 1) ? Kh : Vh;
    __nv_bfloat16* Cl = (z == 0) ? Ql : (z == 1) ? Kl : Vl;

    const int tid = threadIdx.x, wid = tid >> 5, lane = tid & 31;
    const int g = lane >> 2, t = lane & 3;
    const int lrow = lane & 15, lhalf = (lane >> 4) << 3;
    const int bm = blockIdx.y * 128, bn = blockIdx.x * 128;
    const int wm = (wid & 3) * 32, wn = (wid >> 2) * 64;

    const int cid0 = tid * 2;
    const int lr0 = cid0 >> 2, ls0 = (cid0 & 3) * 8;
    const int ls1 = ls0 + 8;
    const uint32_t o0 = (uint32_t)(lr0 * GLD + ls0) * 2;
    const uint32_t o1 = (uint32_t)(lr0 * GLD + ls1) * 2;

    float acc[2][8][4] = {};

    GEMM_MAINLOOP(Ah, Al, Bh, Bl)

    // Epilogue
#pragma unroll
    for (int mf = 0; mf < 2; ++mf) {
#pragma unroll
        for (int nf = 0; nf < 8; ++nf) {
            const int row0 = bm + wm + mf * 16 + g;
            const int col = bn + wn + nf * 8 + 2 * t;
            float2 bvv = *(const float2*)&bias[col];
            float v0 = acc[mf][nf][0] + bvv.x, v1 = acc[mf][nf][1] + bvv.y;
            float v2 = acc[mf][nf][2] + bvv.x, v3 = acc[mf][nf][3] + bvv.y;
            size_t q0 = (size_t)row0 * DM + col;
            size_t q1 = (size_t)(row0 + 8) * DM + col;
            if (z == 0) {
                *(float2*)&Qp[q0] = make_float2(v0, v1);
                *(float2*)&Qp[q1] = make_float2(v2, v3);
            }
            uint32_t h, l;
            split_pair(v0, v1, h, l);
            *(uint32_t*)&Ch[q0] = h; *(uint32_t*)&Cl[q0] = l;
            split_pair(v2, v3, h, l);
            *(uint32_t*)&Ch[q1] = h; *(uint32_t*)&Cl[q1] = l;
        }
    }
}

// ===========================================================================
// MLP GEMM: U = R + relu(A @ Wo + bo)
// ===========================================================================
__global__ __launch_bounds__(256, 2) void gemm_mlp(
    const __nv_bfloat16* __restrict__ Ah, const __nv_bfloat16* __restrict__ Al,
    const __nv_bfloat16* __restrict__ Bh, const __nv_bfloat16* __restrict__ Bl,
    const float* __restrict__ bias, const float* __restrict__ R,
    float* __restrict__ C)
{
    extern __shared__ __nv_bfloat16 gsm[];
    const uint32_t base = smem_u32(gsm);

    const int tid = threadIdx.x, wid = tid >> 5, lane = tid & 31;
    const int g = lane >> 2, t = lane & 3;
    const int lrow = lane & 15, lhalf = (lane >> 4) << 3;
    const int bm = blockIdx.y * 128, bn = blockIdx.x * 128;
    const int wm = (wid & 3) * 32, wn = (wid >> 2) * 64;

    const int cid0 = tid * 2;
    const int lr0 = cid0 >> 2, ls0 = (cid0 & 3) * 8;
    const int ls1 = ls0 + 8;
    const uint32_t o0 = (uint32_t)(lr0 * GLD + ls0) * 2;
    const uint32_t o1 = (uint32_t)(lr0 * GLD + ls1) * 2;

    float acc[2][8][4] = {};

    GEMM_MAINLOOP(Ah, Al, Bh, Bl)

#pragma unroll
    for (int mf = 0; mf < 2; ++mf) {
#pragma unroll
        for (int nf = 0; nf < 8; ++nf) {
            const int row0 = bm + wm + mf * 16 + g;
            const int col = bn + wn + nf * 8 + 2 * t;
            float2 bvv = *(const float2*)&bias[col];
            float v0 = acc[mf][nf][0] + bvv.x, v1 = acc[mf][nf][1] + bvv.y;
            float v2 = acc[mf][nf][2] + bvv.x, v3 = acc[mf][nf][3] + bvv.y;
            size_t q0 = (size_t)row0 * DM + col;
            size_t q1 = (size_t)(row0 + 8) * DM + col;
            float2 r0 = *(const float2*)&R[q0];
            float2 r1 = *(const float2*)&R[q1];
            v0 = r0.x + fmaxf(v0, 0.f); v1 = r0.y + fmaxf(v1, 0.f);
            v2 = r1.x + fmaxf(v2, 0.f); v3 = r1.y + fmaxf(v3, 0.f);
            *(float2*)&C[q0] = make_float2(v0, v1);
            *(float2*)&C[q1] = make_float2(v2, v3);
        }
    }
}

// ===========================================================================
// Attention: CTA = 128 q-rows x (head, batch); 16 key-chunks of 64,
// cp.async 3-stage pipeline; Q fragments register-resident; one barrier/chunk.
// ===========================================================================
#define ATLD 72
#define ATILE (64 * ATLD)          // elems per 64-row tile
#define ASTG  (4 * ATILE)          // elems per stage (KH,KL,VH,VL)
#define A_SMEM (3 * ASTG * 2)      // 110592 bytes

__global__ __launch_bounds__(256, 2) void attn_mma(
    const float* __restrict__ Qp,
    const __nv_bfloat16* __restrict__ Qh, const __nv_bfloat16* __restrict__ Ql,
    const __nv_bfloat16* __restrict__ Kh, const __nv_bfloat16* __restrict__ Kl,
    const __nv_bfloat16* __restrict__ Vh, const __nv_bfloat16* __restrict__ Vl,
    float* __restrict__ O)
{
    extern __shared__ char sm[];
    const uint32_t sb = smem_u32(sm);
    const int tid = threadIdx.x, wid = tid >> 5, lane = tid & 31;
    const int g = lane >> 2, t = lane & 3;
    const int lrow = lane & 15, lhalf = (lane >> 4) << 3;
    const int b = blockIdx.z, h = blockIdx.y, q0 = blockIdx.x * 128;

    // ---- Q prologue: stage Q tile in smem, pull fragments to registers ----
    for (int idx = tid; idx < 1024; idx += 256) {
        int r = idx >> 3, s8 = (idx & 7) * 8;
        size_t go = ((size_t)(b * NQ) + q0 + r) * DM + h * HD + s8;
        int e = (r * ATLD + s8) * 2;
        *(uint4*)(sm + e) = *(const uint4*)&Qh[go];
        *(uint4*)(sm + 128 * ATLD * 2 + e) = *(const uint4*)&Ql[go];
    }
    __syncthreads();
    uint32_t aqh[4][4], aql[4][4];
#pragma unroll
    for (int kb = 0; kb < 4; ++kb) {
        uint32_t qro = (uint32_t)((wid * 16 + lrow) * ATLD) * 2 +
                       (uint32_t)(lhalf + kb * 16) * 2;
        ldsm4(aqh[kb], sb + qro);
        ldsm4(aql[kb], sb + 128 * ATLD * 2 + qro);
    }
    __syncthreads();   // Q reads done; smem reusable by pipeline

    // load mapping for a 64-row chunk: 512 16B-chunks per tile; 2 per thread
    const int cid0 = tid * 2;
    const int lr0 = cid0 >> 3, ls0 = (cid0 & 7) * 8;
    const int ls1 = ls0 + 8;
    const uint32_t o0 = (uint32_t)(lr0 * ATLD + ls0) * 2;
    const uint32_t o1 = (uint32_t)(lr0 * ATLD + ls1) * 2;

    float m0 = -1e30f, m1 = -1e30f, l0 = 0.f, l1 = 0.f;
    float oacc[8][4] = {};

    // prologue: issue chunks 0 and 1
#pragma unroll
    for (int pc = 0; pc < 2; ++pc) {
        uint32_t so = sb + pc * (ASTG * 2);
        size_t go = ((size_t)(b * NQ) + pc * 64 + lr0) * DM + h * HD + ls0;
        cpa16(so + o0, Kh + go);                cpa16(so + o1, Kh + go + 8);
        cpa16(so + ATILE*2 + o0, Kl + go);      cpa16(so + ATILE*2 + o1, Kl + go + 8);
        cpa16(so + 2*ATILE*2 + o0, Vh + go);    cpa16(so + 2*ATILE*2 + o1, Vh + go + 8);
        cpa16(so + 3*ATILE*2 + o0, Vl + go);    cpa16(so + 3*ATILE*2 + o1, Vl + go + 8);
        CP_COMMIT();
    }

    for (int kc = 0; kc < 16; ++kc) {
        if (kc < 15) CP_WAIT1(); else CP_WAIT0();
        __syncthreads();   // chunk kc visible; all warps done with buf (kc+2)%3
        if (kc + 2 < 16) {
            uint32_t so = sb + ((kc + 2) % 3) * (ASTG * 2);
            size_t go = ((size_t)(b * NQ) + (kc + 2) * 64 + lr0) * DM + h * HD + ls0;
            cpa16(so + o0, Kh + go);                cpa16(so + o1, Kh + go + 8);
            cpa16(so + ATILE*2 + o0, Kl + go);      cpa16(so + ATILE*2 + o1, Kl + go + 8);
            cpa16(so + 2*ATILE*2 + o0, Vh + go);    cpa16(so + 2*ATILE*2 + o1, Vh + go + 8);
            cpa16(so + 3*ATILE*2 + o0, Vl + go);    cpa16(so + 3*ATILE*2 + o1, Vl + go + 8);
            CP_COMMIT();
        }

        const uint32_t uS = sb + (kc % 3) * (ASTG * 2);
        const uint32_t uKH = uS, uKL = uS + ATILE*2;
        const uint32_t uVH = uS + 2*ATILE*2, uVL = uS + 3*ATILE*2;

        // ---- S = Q K^T (m16 x n64 x k64) ----
        float s[8][4];
#pragma unroll
        for (int nf = 0; nf < 8; ++nf)
#pragma unroll
            for (int e = 0; e < 4; ++e) s[nf][e] = 0.f;

#pragma unroll
        for (int kb = 0; kb < 4; ++kb) {
            const uint32_t cofs = (uint32_t)(lhalf + kb * 16) * 2;
#pragma unroll
            for (int j = 0; j < 4; ++j) {
                uint32_t bh[4], bl[4];
                uint32_t kro = (uint32_t)((j * 16 + lrow) * ATLD) * 2 + cofs;
                ldsm4(bh, uKH + kro);
                ldsm4(bl, uKL + kro);
                mma16816(s[2 * j],     aqh[kb], bh[0], bh[2]);
                mma16816(s[2 * j + 1], aqh[kb], bh[1], bh[3]);
                mma16816(s[2 * j],     aqh[kb], bl[0], bl[2]);
                mma16816(s[2 * j + 1], aqh[kb], bl[1], bl[3]);
                mma16816(s[2 * j],     aql[kb], bh[0], bh[2]);
                mma16816(s[2 * j + 1], aql[kb], bh[1], bh[3]);
            }
        }

        // ---- online softmax (rows g and g+8) ----
        const float scale = 0.125f;
        float rm0 = -1e30f, rm1 = -1e30f;
#pragma unroll
        for (int nf = 0; nf < 8; ++nf) {
            rm0 = fmaxf(rm0, fmaxf(s[nf][0], s[nf][1]));
            rm1 = fmaxf(rm1, fmaxf(s[nf][2], s[nf][3]));
        }
        rm0 = fmaxf(rm0, __shfl_xor_sync(0xffffffffu, rm0, 1));
        rm0 = fmaxf(rm0, __shfl_xor_sync(0xffffffffu, rm0, 2));
        rm1 = fmaxf(rm1, __shfl_xor_sync(0xffffffffu, rm1, 1));
        rm1 = fmaxf(rm1, __shfl_xor_sync(0xffffffffu, rm1, 2));
        float mn0 = fmaxf(m0, rm0 * scale);
        float mn1 = fmaxf(m1, rm1 * scale);
        float al0 = __expf(m0 - mn0);
        float al1 = __expf(m1 - mn1);
        float sum0 = 0.f, sum1 = 0.f;
#pragma unroll
        for (int nf = 0; nf < 8; ++nf) {
            s[nf][0] = __expf(fmaf(s[nf][0], scale, -mn0));
            s[nf][1] = __expf(fmaf(s[nf][1], scale, -mn0));
            s[nf][2] = __expf(fmaf(s[nf][2], scale, -mn1));
            s[nf][3] = __expf(fmaf(s[nf][3], scale, -mn1));
            sum0 += s[nf][0] + s[nf][1];
            sum1 += s[nf][2] + s[nf][3];
        }
        sum0 += __shfl_xor_sync(0xffffffffu, sum0, 1);
        sum0 += __shfl_xor_sync(0xffffffffu, sum0, 2);
        sum1 += __shfl_xor_sync(0xffffffffu, sum1, 1);
        sum1 += __shfl_xor_sync(0xffffffffu, sum1, 2);
        l0 = l0 * al0 + sum0;
        l1 = l1 * al1 + sum1;
        m0 = mn0; m1 = mn1;
#pragma unroll
        for (int nf = 0; nf < 8; ++nf) {
            oacc[nf][0] *= al0; oacc[nf][1] *= al0;
            oacc[nf][2] *= al1; oacc[nf][3] *= al1;
        }

        // ---- O += P V (m16 x n64 x k64), V frags via ldmatrix.trans ----
#pragma unroll
        for (int kb2 = 0; kb2 < 4; ++kb2) {
            uint32_t aph[4], apl[4];
            {
                const float* p0 = s[2 * kb2];
                const float* p1 = s[2 * kb2 + 1];
                split_pair(p0[0], p0[1], aph[0], apl[0]);
                split_pair(p0[2], p0[3], aph[1], apl[1]);
                split_pair(p1[0], p1[1], aph[2], apl[2]);
                split_pair(p1[2], p1[3], aph[3], apl[3]);
            }
#pragma unroll
            for (int j2 = 0; j2 < 4; ++j2) {
                uint32_t vh[4], vl[4];
                uint32_t vro = (uint32_t)(((kb2 * 16 + lrow) * ATLD) +
                                          j2 * 16 + lhalf) * 2;
                ldsm4t(vh, uVH + vro);
                ldsm4t(vl, uVL + vro);
                mma16816(oacc[2 * j2],     aph, vh[0], vh[1]);
                mma16816(oacc[2 * j2 + 1], aph, vh[2], vh[3]);
                mma16816(oacc[2 * j2],     aph, vl[0], vl[1]);
                mma16816(oacc[2 * j2 + 1], aph, vl[2], vl[3]);
                mma16816(oacc[2 * j2],     apl, vh[0], vh[1]);
                mma16816(oacc[2 * j2 + 1], apl, vh[2], vh[3]);
            }
        }
    }

    // ---- epilogue: normalize + Q residual ----
    const float inv0 = 1.f / l0, inv1 = 1.f / l1;
    const int r0 = q0 + wid * 16 + g;
#pragma unroll
    for (int nf = 0; nf < 8; ++nf) {
        const int d0 = nf * 8 + 2 * t;
        size_t oo0 = ((size_t)(b * NQ) + r0) * DM + h * HD + d0;
        size_t oo1 = oo0 + (size_t)8 * DM;
        float2 q0v = *(const float2*)&Qp[oo0];
        float2 q1v = *(const float2*)&Qp[oo1];
        *(float2*)&O[oo0] = make_float2(fmaf(oacc[nf][0], inv0, q0v.x),
                                        fmaf(oacc[nf][1], inv0, q0v.y));
        *(float2*)&O[oo1] = make_float2(fmaf(oacc[nf][2], inv1, q1v.x),
                                        fmaf(oacc[nf][3], inv1, q1v.y));
    }
}

// ===========================================================================
// LayerNorm (warp per row). EMIT=1 additionally writes bf16 hi/lo split.
// ===========================================================================
template <int EMIT>
__global__ __launch_bounds__(256) void ln_kernel(
    const float* __restrict__ X, const float* __restrict__ gam,
    const float* __restrict__ bet, float* __restrict__ Y,
    __nv_bfloat16* __restrict__ Yh, __nv_bfloat16* __restrict__ Yl)
{
    const int row = blockIdx.x * 8 + (threadIdx.x >> 5);
    const int lane = threadIdx.x & 31;
    const float* x = X + (size_t)row * DM;

    float v[16];
    float sum = 0.f, ss = 0.f;
#pragma unroll
    for (int i = 0; i < 4; ++i) {
        float4 tv = *(const float4*)(x + i * 128 + lane * 4);
        v[i * 4 + 0] = tv.x; v[i * 4 + 1] = tv.y;
        v[i * 4 + 2] = tv.z; v[i * 4 + 3] = tv.w;
        sum += tv.x + tv.y + tv.z + tv.w;
        ss += tv.x * tv.x + tv.y * tv.y + tv.z * tv.z + tv.w * tv.w;
    }
#pragma unroll
    for (int m = 16; m >= 1; m >>= 1) {
        sum += __shfl_xor_sync(0xffffffffu, sum, m);
        ss += __shfl_xor_sync(0xffffffffu, ss, m);
    }
    const float mean = sum * (1.f / DM);
    const float var = ss * (1.f / DM) - mean * mean;
    const float inv = rsqrtf(var + 1e-5f);

    float* y = Y + (size_t)row * DM;
#pragma unroll
    for (int i = 0; i < 4; ++i) {
        const int col = i * 128 + lane * 4;
        float4 gv = *(const float4*)(gam + col);
        float4 bb = *(const float4*)(bet + col);
        float4 o;
        o.x = (v[i * 4 + 0] - mean) * inv * gv.x + bb.x;
        o.y = (v[i * 4 + 1] - mean) * inv * gv.y + bb.y;
        o.z = (v[i * 4 + 2] - mean) * inv * gv.z + bb.z;
        o.w = (v[i * 4 + 3] - mean) * inv * gv.w + bb.w;
        *(float4*)(y + col) = o;
        if (EMIT) {
            uint32_t h0, l0, h1, l1;
            split_pair(o.x, o.y, h0, l0);
            split_pair(o.z, o.w, h1, l1);
            size_t e = (size_t)row * DM + col;
            *(uint2*)&Yh[e] = make_uint2(h0, h1);
            *(uint2*)&Yl[e] = make_uint2(l0, l1);
        }
    }
}

// ===========================================================================
extern "C" void kernel_launch(void* const* d_in, const int* in_sizes, int n_in,
                              void* d_out, int out_size)
{
    const float* Q  = (const float*)d_in[0];
    const float* K  = (const float*)d_in[1];
    const float* Wq = (const float*)d_in[2];
    const float* bq = (const float*)d_in[3];
    const float* Wk = (const float*)d_in[4];
    const float* bk = (const float*)d_in[5];
    const float* Wv = (const float*)d_in[6];
    const float* bv = (const float*)d_in[7];
    const float* Wo = (const float*)d_in[8];
    const float* bo = (const float*)d_in[9];
    const float* g0 = (const float*)d_in[10];
    const float* b0 = (const float*)d_in[11];
    const float* g1 = (const float*)d_in[12];
    const float* b1 = (const float*)d_in[13];
    float* out = (float*)d_out;

    float *Qp, *O, *T, *U;
    __nv_bfloat16 *Ah, *Al, *Kbh, *Kbl, *Qh, *Ql, *Kh, *Kl, *Vh, *Vl, *Wth, *Wtl;
    cudaGetSymbolAddress((void**)&Qp, g_Qp);
    cudaGetSymbolAddress((void**)&O,  g_O);
    cudaGetSymbolAddress((void**)&T,  g_T);
    cudaGetSymbolAddress((void**)&U,  g_U);
    cudaGetSymbolAddress((void**)&Ah, g_Ah);
    cudaGetSymbolAddress((void**)&Al, g_Al);
    cudaGetSymbolAddress((void**)&Kbh, g_Kbh);
    cudaGetSymbolAddress((void**)&Kbl, g_Kbl);
    cudaGetSymbolAddress((void**)&Qh, g_Qh);
    cudaGetSymbolAddress((void**)&Ql, g_Ql);
    cudaGetSymbolAddress((void**)&Kh, g_Kh);
    cudaGetSymbolAddress((void**)&Kl, g_Kl);
    cudaGetSymbolAddress((void**)&Vh, g_Vh);
    cudaGetSymbolAddress((void**)&Vl, g_Vl);
    cudaGetSymbolAddress((void**)&Wth, g_Wth);
    cudaGetSymbolAddress((void**)&Wtl, g_Wtl);

    static int attr_set = 0;
    if (!attr_set) {
        cudaFuncSetAttribute(attn_mma,
            cudaFuncAttributeMaxDynamicSharedMemorySize, A_SMEM);
        cudaFuncSetAttribute(gemm_qkv,
            cudaFuncAttributeMaxDynamicSharedMemorySize, G_SMEM);
        cudaFuncSetAttribute(gemm_mlp,
            cudaFuncAttributeMaxDynamicSharedMemorySize, G_SMEM);
        attr_set = 1;
    }

    const int WSZ = DM * DM;

    // #0: input splits (Q and K fused)
    cvt_split2<<<dim3(512, 2), 256>>>((const float4*)Q, Ah, Al,
                                      (const float4*)K, Kbh, Kbl, TOT / 4);
    // #1: all 4 weight transpose+splits fused
    cvt_wt4<<<dim3(16, 16, 4), dim3(32, 8)>>>(Wq, Wk, Wv, Wo, Wth, Wtl);

    // #2: fused QKV projections (768 CTAs in one grid)
    gemm_qkv<<<dim3(DM / 128, (BT * NQ) / 128, 3), 256, G_SMEM>>>(
        Ah, Al, Kbh, Kbl, Wth, Wtl, bq, bk, bv,
        Qp, Qh, Ql, Kh, Kl, Vh, Vl);

    // #3: attention + Q residual
    attn_mma<<<dim3(NQ / 128, HEADS, BT), 256, A_SMEM>>>(Qp, Qh, Ql, Kh, Kl,
                                                         Vh, Vl, O);

    // #4: LN0 (emit bf16 split of T for the MLP GEMM)
    ln_kernel<1><<<(BT * NQ) / 8, 256>>>(O, g0, b0, T, Ah, Al);

    // #5: U = T + relu(T @ Wo + bo)
    gemm_mlp<<<dim3(DM / 128, (BT * NQ) / 128), 256, G_SMEM>>>(
        Ah, Al, Wth + 3 * WSZ, Wtl + 3 * WSZ, bo, T, U);

    // #6: LN1 -> out
    ln_kernel<0><<<(BT * NQ) / 8, 256>>>(U, g1, b1, out, nullptr, nullptr);
}

// round 11
// speedup vs baseline: 1.1117x; 1.0963x over previous
#include <cuda_runtime.h>
#include <cuda_bf16.h>
#include <math.h>
#include <stdint.h>

#define BT 8
#define NQ 1024
#define DM 512
#define HEADS 8
#define HD 64
#define TOT (BT*NQ*DM)

// fp32 scratch
__device__ float g_Qp[TOT];
__device__ float g_O [TOT];
__device__ float g_T [TOT];
__device__ float g_U [TOT];
// bf16 split scratch
__device__ __nv_bfloat16 g_Ah[TOT], g_Al[TOT];     // raw-Q splits, then T splits
__device__ __nv_bfloat16 g_Kbh[TOT], g_Kbl[TOT];   // raw-K splits
__device__ __nv_bfloat16 g_Qh[TOT], g_Ql[TOT];     // projected Q splits
__device__ __nv_bfloat16 g_Kh[TOT], g_Kl[TOT];     // projected K splits
__device__ __nv_bfloat16 g_Vh[TOT], g_Vl[TOT];     // projected V splits
__device__ __nv_bfloat16 g_Wth[4][DM*DM], g_Wtl[4][DM*DM]; // transposed weights

// ===========================================================================
// Helpers
// ===========================================================================
__device__ __forceinline__ uint32_t smem_u32(const void* p) {
    uint32_t a;
    asm("{ .reg .u64 t; cvta.to.shared.u64 t, %1; cvt.u32.u64 %0, t; }"
        : "=r"(a) : "l"(p));
    return a;
}

__device__ __forceinline__ void ldsm4(uint32_t r[4], uint32_t addr) {
    asm volatile("ldmatrix.sync.aligned.m8n8.x4.shared.b16 {%0,%1,%2,%3}, [%4];"
        : "=r"(r[0]), "=r"(r[1]), "=r"(r[2]), "=r"(r[3]) : "r"(addr));
}
__device__ __forceinline__ void ldsm4t(uint32_t r[4], uint32_t addr) {
    asm volatile("ldmatrix.sync.aligned.m8n8.x4.trans.shared.b16 {%0,%1,%2,%3}, [%4];"
        : "=r"(r[0]), "=r"(r[1]), "=r"(r[2]), "=r"(r[3]) : "r"(addr));
}

__device__ __forceinline__ void mma16816(float c[4], const uint32_t a[4],
                                         uint32_t b0, uint32_t b1) {
    asm volatile(
        "mma.sync.aligned.m16n8k16.row.col.f32.bf16.bf16.f32 "
        "{%0,%1,%2,%3}, {%4,%5,%6,%7}, {%8,%9}, {%0,%1,%2,%3};"
        : "+f"(c[0]), "+f"(c[1]), "+f"(c[2]), "+f"(c[3])
        : "r"(a[0]), "r"(a[1]), "r"(a[2]), "r"(a[3]), "r"(b0), "r"(b1));
}

__device__ __forceinline__ uint32_t packbf(float x, float y) {
    __nv_bfloat162 h = __floats2bfloat162_rn(x, y);
    return *reinterpret_cast<uint32_t*>(&h);
}

__device__ __forceinline__ void split_pair(float x, float y,
                                           uint32_t& hi, uint32_t& lo) {
    __nv_bfloat162 h = __floats2bfloat162_rn(x, y);
    float rx = x - __bfloat162float(h.x);
    float ry = y - __bfloat162float(h.y);
    hi = *reinterpret_cast<uint32_t*>(&h);
    lo = packbf(rx, ry);
}

__device__ __forceinline__ void cpa16(uint32_t dst, const void* src) {
    asm volatile("cp.async.ca.shared.global [%0], [%1], 16;"
                 :: "r"(dst), "l"(src));
}
#define CP_COMMIT() asm volatile("cp.async.commit_group;" ::: "memory")
#define CP_WAIT0()  asm volatile("cp.async.wait_group 0;" ::: "memory")
#define CP_WAIT1()  asm volatile("cp.async.wait_group 1;" ::: "memory")

// ===========================================================================
// Fused split-convert: two tensors fp32 -> bf16 hi/lo (blockIdx.y selects)
// ===========================================================================
__global__ __launch_bounds__(256) void cvt_split2(
    const float4* __restrict__ X0, __nv_bfloat16* __restrict__ X0h,
    __nv_bfloat16* __restrict__ X0l,
    const float4* __restrict__ X1, __nv_bfloat16* __restrict__ X1h,
    __nv_bfloat16* __restrict__ X1l, int n4)
{
    const float4* X = blockIdx.y ? X1 : X0;
    __nv_bfloat16* Xh = blockIdx.y ? X1h : X0h;
    __nv_bfloat16* Xl = blockIdx.y ? X1l : X0l;
    for (int i = blockIdx.x * blockDim.x + threadIdx.x; i < n4;
         i += gridDim.x * blockDim.x) {
        float4 v = X[i];
        uint32_t h0, l0, h1, l1;
        split_pair(v.x, v.y, h0, l0);
        split_pair(v.z, v.w, h1, l1);
        *(uint2*)&Xh[4 * i] = make_uint2(h0, h1);
        *(uint2*)&Xl[4 * i] = make_uint2(l0, l1);
    }
}

// Fused weight transpose + split for all 4 weights (blockIdx.z selects)
__global__ __launch_bounds__(256) void cvt_wt4(
    const float* __restrict__ W0, const float* __restrict__ W1,
    const float* __restrict__ W2, const float* __restrict__ W3,
    __nv_bfloat16* __restrict__ WthB, __nv_bfloat16* __restrict__ WtlB)
{
    const float* W = (blockIdx.z == 0) ? W0 : (blockIdx.z == 1) ? W1 :
                     (blockIdx.z == 2) ? W2 : W3;
    __nv_bfloat16* Wth = WthB + (size_t)blockIdx.z * DM * DM;
    __nv_bfloat16* Wtl = WtlB + (size_t)blockIdx.z * DM * DM;

    __shared__ float tile[32][33];
    const int tx = threadIdx.x, ty = threadIdx.y;  // 32 x 8
    const int kb = blockIdx.y * 32, nb = blockIdx.x * 32;
#pragma unroll
    for (int i = 0; i < 32; i += 8)
        tile[ty + i][tx] = W[(size_t)(kb + ty + i) * DM + nb + tx];
    __syncthreads();
#pragma unroll
    for (int i = 0; i < 32; i += 8) {
        float v = tile[tx][ty + i];
        __nv_bfloat16 h = __float2bfloat16(v);
        size_t o = (size_t)(nb + ty + i) * DM + kb + tx;
        Wth[o] = h;
        Wtl[o] = __float2bfloat16(v - __bfloat162float(h));
    }
}

// ===========================================================================
// Shared GEMM mainloop: cp.async 2-stage, fragment double-buffered,
// cp.async issues interleaved into the first kb's MMA blocks.
// ===========================================================================
#define GLD 40                 // smem row stride (bf16)
#define GSTG (128 * GLD)       // elems per array per stage
#define G_SMEM (2 * 4 * GSTG * 2)   // bytes = 81920

__device__ __forceinline__ void gemm_mainloop(
    uint32_t base,
    const __nv_bfloat16* __restrict__ Ah, const __nv_bfloat16* __restrict__ Al,
    const __nv_bfloat16* __restrict__ Bh, const __nv_bfloat16* __restrict__ Bl,
    int bm, int bn, int wm, int wn, int lrow, int lhalf,
    int lr0, int ls0, uint32_t o0, uint32_t o1,
    float (&acc)[2][8][4])
{
    // prologue: issue chunk 0
    {
        uint32_t so = base;
        size_t ga0 = (size_t)(bm + lr0) * DM + ls0;
        size_t gb0 = (size_t)(bn + lr0) * DM + ls0;
        cpa16(so + o0, Ah + ga0);            cpa16(so + o1, Ah + ga0 + 8);
        cpa16(so + GSTG*2 + o0, Al + ga0);   cpa16(so + GSTG*2 + o1, Al + ga0 + 8);
        cpa16(so + 2*GSTG*2 + o0, Bh + gb0); cpa16(so + 2*GSTG*2 + o1, Bh + gb0 + 8);
        cpa16(so + 3*GSTG*2 + o0, Bl + gb0); cpa16(so + 3*GSTG*2 + o1, Bl + gb0 + 8);
        CP_COMMIT();
    }

    for (int c = 0; c < 16; ++c) {
        CP_WAIT0();
        __syncthreads();

        const uint32_t uS = base + (c & 1) * (4 * GSTG * 2);
        const uint32_t uAh = uS, uAl = uS + GSTG*2;
        const uint32_t uBh = uS + 2*GSTG*2, uBl = uS + 3*GSTG*2;

        const bool pf = (c + 1 < 16);
        const int k0n = (c + 1) * 32;
        const uint32_t son = base + ((c + 1) & 1) * (4 * GSTG * 2);
        const size_t gan = (size_t)(bm + lr0) * DM + k0n + ls0;
        const size_t gbn = (size_t)(bn + lr0) * DM + k0n + ls0;

#pragma unroll
        for (int kb = 0; kb < 2; ++kb) {
            const uint32_t cofs = (uint32_t)(lhalf + kb * 16) * 2;
            uint32_t ah[2][4], al[2][4];
#pragma unroll
            for (int mf = 0; mf < 2; ++mf) {
                uint32_t rofs = (uint32_t)((wm + mf * 16 + lrow) * GLD) * 2 + cofs;
                ldsm4(ah[mf], uAh + rofs);
                ldsm4(al[mf], uAl + rofs);
            }
            // fragment double buffer for B
            uint32_t bh2[2][4], bl2[2][4];
            {
                uint32_t rofs = (uint32_t)((wn + lrow) * GLD) * 2 + cofs;
                ldsm4(bh2[0], uBh + rofs);
                ldsm4(bl2[0], uBl + rofs);
            }
#pragma unroll
            for (int j = 0; j < 4; ++j) {
                if (j < 3) {
                    uint32_t rofs = (uint32_t)((wn + (j + 1) * 16 + lrow) * GLD) * 2 + cofs;
                    ldsm4(bh2[(j + 1) & 1], uBh + rofs);
                    ldsm4(bl2[(j + 1) & 1], uBl + rofs);
                }
                // interleave next-chunk cp.async issues (kb 0, one pair per j)
                if (kb == 0 && pf) {
                    if (j == 0) { cpa16(son + o0, Ah + gan);
                                  cpa16(son + o1, Ah + gan + 8); }
                    if (j == 1) { cpa16(son + GSTG*2 + o0, Al + gan);
                                  cpa16(son + GSTG*2 + o1, Al + gan + 8); }
                    if (j == 2) { cpa16(son + 2*GSTG*2 + o0, Bh + gbn);
                                  cpa16(son + 2*GSTG*2 + o1, Bh + gbn + 8); }
                    if (j == 3) { cpa16(son + 3*GSTG*2 + o0, Bl + gbn);
                                  cpa16(son + 3*GSTG*2 + o1, Bl + gbn + 8);
                                  CP_COMMIT(); }
                }
                const uint32_t* bhf = bh2[j & 1];
                const uint32_t* blf = bl2[j & 1];
                // term hh (both m-frags)
                mma16816(acc[0][2*j],   ah[0], bhf[0], bhf[2]);
                mma16816(acc[0][2*j+1], ah[0], bhf[1], bhf[3]);
                mma16816(acc[1][2*j],   ah[1], bhf[0], bhf[2]);
                mma16816(acc[1][2*j+1], ah[1], bhf[1], bhf[3]);
                // term hl
                mma16816(acc[0][2*j],   ah[0], blf[0], blf[2]);
                mma16816(acc[0][2*j+1], ah[0], blf[1], blf[3]);
                mma16816(acc[1][2*j],   ah[1], blf[0], blf[2]);
                mma16816(acc[1][2*j+1], ah[1], blf[1], blf[3]);
                // term lh
                mma16816(acc[0][2*j],   al[0], bhf[0], bhf[2]);
                mma16816(acc[0][2*j+1], al[0], bhf[1], bhf[3]);
                mma16816(acc[1][2*j],   al[1], bhf[0], bhf[2]);
                mma16816(acc[1][2*j+1], al[1], bhf[1], bhf[3]);
            }
        }
    }
}

// ===========================================================================
// Fused QKV projection GEMM: blockIdx.z selects (activation, weight, outputs)
// ===========================================================================
__global__ __launch_bounds__(256, 2) void gemm_qkv(
    const __nv_bfloat16* __restrict__ QAh, const __nv_bfloat16* __restrict__ QAl,
    const __nv_bfloat16* __restrict__ KAh, const __nv_bfloat16* __restrict__ KAl,
    const __nv_bfloat16* __restrict__ WthB, const __nv_bfloat16* __restrict__ WtlB,
    const float* __restrict__ bq, const float* __restrict__ bk,
    const float* __restrict__ bv,
    float* __restrict__ Qp,
    __nv_bfloat16* __restrict__ Qh, __nv_bfloat16* __restrict__ Ql,
    __nv_bfloat16* __restrict__ Kh, __nv_bfloat16* __restrict__ Kl,
    __nv_bfloat16* __restrict__ Vh, __nv_bfloat16* __restrict__ Vl)
{
    extern __shared__ __nv_bfloat16 gsm[];
    const uint32_t base = smem_u32(gsm);

    const int z = blockIdx.z;
    const __nv_bfloat16* Ah = (z == 0) ? QAh : KAh;
    const __nv_bfloat16* Al = (z == 0) ? QAl : KAl;
    const __nv_bfloat16* Bh = WthB + (size_t)z * DM * DM;
    const __nv_bfloat16* Bl = WtlB + (size_t)z * DM * DM;
    const float* bias = (z == 0) ? bq : (z == 1) ? bk : bv;
    __nv_bfloat16* Ch = (z == 0) ? Qh : (z == 1) ? Kh : Vh;
    __nv_bfloat16* Cl = (z == 0) ? Ql : (z == 1) ? Kl : Vl;

    const int tid = threadIdx.x, wid = tid >> 5, lane = tid & 31;
    const int g = lane >> 2, t = lane & 3;
    const int lrow = lane & 15, lhalf = (lane >> 4) << 3;
    const int bm = blockIdx.y * 128, bn = blockIdx.x * 128;
    const int wm = (wid & 3) * 32, wn = (wid >> 2) * 64;

    const int cid0 = tid * 2;
    const int lr0 = cid0 >> 2, ls0 = (cid0 & 3) * 8;
    const uint32_t o0 = (uint32_t)(lr0 * GLD + ls0) * 2;
    const uint32_t o1 = (uint32_t)(lr0 * GLD + ls0 + 8) * 2;

    float acc[2][8][4] = {};

    gemm_mainloop(base, Ah, Al, Bh, Bl, bm, bn, wm, wn, lrow, lhalf,
                  lr0, ls0, o0, o1, acc);

    // Epilogue
#pragma unroll
    for (int mf = 0; mf < 2; ++mf) {
#pragma unroll
        for (int nf = 0; nf < 8; ++nf) {
            const int row0 = bm + wm + mf * 16 + g;
            const int col = bn + wn + nf * 8 + 2 * t;
            float2 bvv = *(const float2*)&bias[col];
            float v0 = acc[mf][nf][0] + bvv.x, v1 = acc[mf][nf][1] + bvv.y;
            float v2 = acc[mf][nf][2] + bvv.x, v3 = acc[mf][nf][3] + bvv.y;
            size_t q0 = (size_t)row0 * DM + col;
            size_t q1 = (size_t)(row0 + 8) * DM + col;
            if (z == 0) {
                *(float2*)&Qp[q0] = make_float2(v0, v1);
                *(float2*)&Qp[q1] = make_float2(v2, v3);
            }
            uint32_t h, l;
            split_pair(v0, v1, h, l);
            *(uint32_t*)&Ch[q0] = h; *(uint32_t*)&Cl[q0] = l;
            split_pair(v2, v3, h, l);
            *(uint32_t*)&Ch[q1] = h; *(uint32_t*)&Cl[q1] = l;
        }
    }
}

// ===========================================================================
// MLP GEMM: U = R + relu(A @ Wo + bo)
// ===========================================================================
__global__ __launch_bounds__(256, 2) void gemm_mlp(
    const __nv_bfloat16* __restrict__ Ah, const __nv_bfloat16* __restrict__ Al,
    const __nv_bfloat16* __restrict__ Bh, const __nv_bfloat16* __restrict__ Bl,
    const float* __restrict__ bias, const float* __restrict__ R,
    float* __restrict__ C)
{
    extern __shared__ __nv_bfloat16 gsm[];
    const uint32_t base = smem_u32(gsm);

    const int tid = threadIdx.x, wid = tid >> 5, lane = tid & 31;
    const int g = lane >> 2, t = lane & 3;
    const int lrow = lane & 15, lhalf = (lane >> 4) << 3;
    const int bm = blockIdx.y * 128, bn = blockIdx.x * 128;
    const int wm = (wid & 3) * 32, wn = (wid >> 2) * 64;

    const int cid0 = tid * 2;
    const int lr0 = cid0 >> 2, ls0 = (cid0 & 3) * 8;
    const uint32_t o0 = (uint32_t)(lr0 * GLD + ls0) * 2;
    const uint32_t o1 = (uint32_t)(lr0 * GLD + ls0 + 8) * 2;

    float acc[2][8][4] = {};

    gemm_mainloop(base, Ah, Al, Bh, Bl, bm, bn, wm, wn, lrow, lhalf,
                  lr0, ls0, o0, o1, acc);

#pragma unroll
    for (int mf = 0; mf < 2; ++mf) {
#pragma unroll
        for (int nf = 0; nf < 8; ++nf) {
            const int row0 = bm + wm + mf * 16 + g;
            const int col = bn + wn + nf * 8 + 2 * t;
            float2 bvv = *(const float2*)&bias[col];
            float v0 = acc[mf][nf][0] + bvv.x, v1 = acc[mf][nf][1] + bvv.y;
            float v2 = acc[mf][nf][2] + bvv.x, v3 = acc[mf][nf][3] + bvv.y;
            size_t q0 = (size_t)row0 * DM + col;
            size_t q1 = (size_t)(row0 + 8) * DM + col;
            float2 r0 = *(const float2*)&R[q0];
            float2 r1 = *(const float2*)&R[q1];
            v0 = r0.x + fmaxf(v0, 0.f); v1 = r0.y + fmaxf(v1, 0.f);
            v2 = r1.x + fmaxf(v2, 0.f); v3 = r1.y + fmaxf(v3, 0.f);
            *(float2*)&C[q0] = make_float2(v0, v1);
            *(float2*)&C[q1] = make_float2(v2, v3);
        }
    }
}

// ===========================================================================
// Attention: CTA = 128 q-rows x (head, batch); 16 key-chunks of 64,
// cp.async 3-stage; Q frags register-resident; fragment double-buffering;
// cp.async issues interleaved into S-loop; V frag preloaded before softmax.
// ===========================================================================
#define ATLD 72
#define ATILE (64 * ATLD)          // elems per 64-row tile
#define ASTG  (4 * ATILE)          // elems per stage (KH,KL,VH,VL)
#define A_SMEM (3 * ASTG * 2)      // 110592 bytes

__global__ __launch_bounds__(256, 2) void attn_mma(
    const float* __restrict__ Qp,
    const __nv_bfloat16* __restrict__ Qh, const __nv_bfloat16* __restrict__ Ql,
    const __nv_bfloat16* __restrict__ Kh, const __nv_bfloat16* __restrict__ Kl,
    const __nv_bfloat16* __restrict__ Vh, const __nv_bfloat16* __restrict__ Vl,
    float* __restrict__ O)
{
    extern __shared__ char sm[];
    const uint32_t sb = smem_u32(sm);
    const int tid = threadIdx.x, wid = tid >> 5, lane = tid & 31;
    const int g = lane >> 2, t = lane & 3;
    const int lrow = lane & 15, lhalf = (lane >> 4) << 3;
    const int b = blockIdx.z, h = blockIdx.y, q0 = blockIdx.x * 128;

    // ---- Q prologue: stage Q tile in smem, pull fragments to registers ----
    for (int idx = tid; idx < 1024; idx += 256) {
        int r = idx >> 3, s8 = (idx & 7) * 8;
        size_t go = ((size_t)(b * NQ) + q0 + r) * DM + h * HD + s8;
        int e = (r * ATLD + s8) * 2;
        *(uint4*)(sm + e) = *(const uint4*)&Qh[go];
        *(uint4*)(sm + 128 * ATLD * 2 + e) = *(const uint4*)&Ql[go];
    }
    __syncthreads();
    uint32_t aqh[4][4], aql[4][4];
#pragma unroll
    for (int kb = 0; kb < 4; ++kb) {
        uint32_t qro = (uint32_t)((wid * 16 + lrow) * ATLD) * 2 +
                       (uint32_t)(lhalf + kb * 16) * 2;
        ldsm4(aqh[kb], sb + qro);
        ldsm4(aql[kb], sb + 128 * ATLD * 2 + qro);
    }
    __syncthreads();   // Q reads done; smem reusable by pipeline

    // load mapping for a 64-row chunk: 512 16B-chunks per tile; 2 per thread
    const int cid0 = tid * 2;
    const int lr0 = cid0 >> 3, ls0 = (cid0 & 7) * 8;
    const uint32_t o0 = (uint32_t)(lr0 * ATLD + ls0) * 2;
    const uint32_t o1 = (uint32_t)(lr0 * ATLD + ls0 + 8) * 2;

    float m0 = -1e30f, m1 = -1e30f, l0 = 0.f, l1 = 0.f;
    float oacc[8][4] = {};

    // prologue: issue chunks 0 and 1
#pragma unroll
    for (int pc = 0; pc < 2; ++pc) {
        uint32_t so = sb + pc * (ASTG * 2);
        size_t go = ((size_t)(b * NQ) + pc * 64 + lr0) * DM + h * HD + ls0;
        cpa16(so + o0, Kh + go);                cpa16(so + o1, Kh + go + 8);
        cpa16(so + ATILE*2 + o0, Kl + go);      cpa16(so + ATILE*2 + o1, Kl + go + 8);
        cpa16(so + 2*ATILE*2 + o0, Vh + go);    cpa16(so + 2*ATILE*2 + o1, Vh + go + 8);
        cpa16(so + 3*ATILE*2 + o0, Vl + go);    cpa16(so + 3*ATILE*2 + o1, Vl + go + 8);
        CP_COMMIT();
    }

    for (int kc = 0; kc < 16; ++kc) {
        if (kc < 15) CP_WAIT1(); else CP_WAIT0();
        __syncthreads();   // chunk kc visible; all warps done with buf (kc+2)%3

        const uint32_t uS = sb + (kc % 3) * (ASTG * 2);
        const uint32_t uKH = uS, uKL = uS + ATILE*2;
        const uint32_t uVH = uS + 2*ATILE*2, uVL = uS + 3*ATILE*2;

        const bool pf = (kc + 2 < 16);
        const uint32_t son = sb + ((kc + 2) % 3) * (ASTG * 2);
        const size_t gon = ((size_t)(b * NQ) + (kc + 2) * 64 + lr0) * DM +
                           h * HD + ls0;

        // ---- S = Q K^T (m16 x n64 x k64), K-fragment double buffer ----
        float s[8][4];
#pragma unroll
        for (int nf = 0; nf < 8; ++nf)
#pragma unroll
            for (int e = 0; e < 4; ++e) s[nf][e] = 0.f;

        uint32_t kh2[2][4], kl2[2][4];
        {
            uint32_t kro = (uint32_t)(lrow * ATLD) * 2 + (uint32_t)lhalf * 2;
            ldsm4(kh2[0], uKH + kro);
            ldsm4(kl2[0], uKL + kro);
        }
#pragma unroll
        for (int kb = 0; kb < 4; ++kb) {
#pragma unroll
            for (int j = 0; j < 4; ++j) {
                const int p = kb * 4 + j;
                if (p < 15) {
                    const int pn = p + 1, kbn = pn >> 2, jn = pn & 3;
                    uint32_t kro = (uint32_t)((jn * 16 + lrow) * ATLD) * 2 +
                                   (uint32_t)(lhalf + kbn * 16) * 2;
                    ldsm4(kh2[pn & 1], uKH + kro);
                    ldsm4(kl2[pn & 1], uKL + kro);
                }
                // interleave next-chunk cp.async issues (kb 0, one pair per j)
                if (kb == 0 && pf) {
                    if (j == 0) { cpa16(son + o0, Kh + gon);
                                  cpa16(son + o1, Kh + gon + 8); }
                    if (j == 1) { cpa16(son + ATILE*2 + o0, Kl + gon);
                                  cpa16(son + ATILE*2 + o1, Kl + gon + 8); }
                    if (j == 2) { cpa16(son + 2*ATILE*2 + o0, Vh + gon);
                                  cpa16(son + 2*ATILE*2 + o1, Vh + gon + 8); }
                    if (j == 3) { cpa16(son + 3*ATILE*2 + o0, Vl + gon);
                                  cpa16(son + 3*ATILE*2 + o1, Vl + gon + 8);
                                  CP_COMMIT(); }
                }
                const uint32_t* bh = kh2[p & 1];
                const uint32_t* bl = kl2[p & 1];
                mma16816(s[2 * j],     aqh[kb], bh[0], bh[2]);
                mma16816(s[2 * j + 1], aqh[kb], bh[1], bh[3]);
                mma16816(s[2 * j],     aqh[kb], bl[0], bl[2]);
                mma16816(s[2 * j + 1], aqh[kb], bl[1], bl[3]);
                mma16816(s[2 * j],     aql[kb], bh[0], bh[2]);
                mma16816(s[2 * j + 1], aql[kb], bh[1], bh[3]);
            }
        }

        // ---- preload first V fragment (overlaps softmax MUFU latency) ----
        uint32_t vh2[2][4], vl2[2][4];
        {
            uint32_t vro = (uint32_t)(lrow * ATLD + lhalf) * 2;
            ldsm4t(vh2[0], uVH + vro);
            ldsm4t(vl2[0], uVL + vro);
        }

        // ---- online softmax (rows g and g+8) ----
        const float scale = 0.125f;
        float rm0 = -1e30f, rm1 = -1e30f;
#pragma unroll
        for (int nf = 0; nf < 8; ++nf) {
            rm0 = fmaxf(rm0, fmaxf(s[nf][0], s[nf][1]));
            rm1 = fmaxf(rm1, fmaxf(s[nf][2], s[nf][3]));
        }
        rm0 = fmaxf(rm0, __shfl_xor_sync(0xffffffffu, rm0, 1));
        rm0 = fmaxf(rm0, __shfl_xor_sync(0xffffffffu, rm0, 2));
        rm1 = fmaxf(rm1, __shfl_xor_sync(0xffffffffu, rm1, 1));
        rm1 = fmaxf(rm1, __shfl_xor_sync(0xffffffffu, rm1, 2));
        float mn0 = fmaxf(m0, rm0 * scale);
        float mn1 = fmaxf(m1, rm1 * scale);
        float al0 = __expf(m0 - mn0);
        float al1 = __expf(m1 - mn1);
        float sum0 = 0.f, sum1 = 0.f;
#pragma unroll
        for (int nf = 0; nf < 8; ++nf) {
            s[nf][0] = __expf(fmaf(s[nf][0], scale, -mn0));
            s[nf][1] = __expf(fmaf(s[nf][1], scale, -mn0));
            s[nf][2] = __expf(fmaf(s[nf][2], scale, -mn1));
            s[nf][3] = __expf(fmaf(s[nf][3], scale, -mn1));
            sum0 += s[nf][0] + s[nf][1];
            sum1 += s[nf][2] + s[nf][3];
        }
        sum0 += __shfl_xor_sync(0xffffffffu, sum0, 1);
        sum0 += __shfl_xor_sync(0xffffffffu, sum0, 2);
        sum1 += __shfl_xor_sync(0xffffffffu, sum1, 1);
        sum1 += __shfl_xor_sync(0xffffffffu, sum1, 2);
        l0 = l0 * al0 + sum0;
        l1 = l1 * al1 + sum1;
        m0 = mn0; m1 = mn1;
#pragma unroll
        for (int nf = 0; nf < 8; ++nf) {
            oacc[nf][0] *= al0; oacc[nf][1] *= al0;
            oacc[nf][2] *= al1; oacc[nf][3] *= al1;
        }

        // ---- O += P V (m16 x n64 x k64), V-fragment double buffer ----
#pragma unroll
        for (int kb2 = 0; kb2 < 4; ++kb2) {
            uint32_t aph[4], apl[4];
            {
                const float* p0 = s[2 * kb2];
                const float* p1 = s[2 * kb2 + 1];
                split_pair(p0[0], p0[1], aph[0], apl[0]);
                split_pair(p0[2], p0[3], aph[1], apl[1]);
                split_pair(p1[0], p1[1], aph[2], apl[2]);
                split_pair(p1[2], p1[3], aph[3], apl[3]);
            }
#pragma unroll
            for (int j2 = 0; j2 < 4; ++j2) {
                const int p = kb2 * 4 + j2;
                if (p < 15) {
                    const int pn = p + 1, kb2n = pn >> 2, j2n = pn & 3;
                    uint32_t vro = (uint32_t)((kb2n * 16 + lrow) * ATLD +
                                              j2n * 16 + lhalf) * 2;
                    ldsm4t(vh2[pn & 1], uVH + vro);
                    ldsm4t(vl2[pn & 1], uVL + vro);
                }
                const uint32_t* vh = vh2[p & 1];
                const uint32_t* vl = vl2[p & 1];
                mma16816(oacc[2 * j2],     aph, vh[0], vh[1]);
                mma16816(oacc[2 * j2 + 1], aph, vh[2], vh[3]);
                mma16816(oacc[2 * j2],     aph, vl[0], vl[1]);
                mma16816(oacc[2 * j2 + 1], aph, vl[2], vl[3]);
                mma16816(oacc[2 * j2],     apl, vh[0], vh[1]);
                mma16816(oacc[2 * j2 + 1], apl, vh[2], vh[3]);
            }
        }
    }

    // ---- epilogue: normalize + Q residual ----
    const float inv0 = 1.f / l0, inv1 = 1.f / l1;
    const int r0 = q0 + wid * 16 + g;
#pragma unroll
    for (int nf = 0; nf < 8; ++nf) {
        const int d0 = nf * 8 + 2 * t;
        size_t oo0 = ((size_t)(b * NQ) + r0) * DM + h * HD + d0;
        size_t oo1 = oo0 + (size_t)8 * DM;
        float2 q0v = *(const float2*)&Qp[oo0];
        float2 q1v = *(const float2*)&Qp[oo1];
        *(float2*)&O[oo0] = make_float2(fmaf(oacc[nf][0], inv0, q0v.x),
                                        fmaf(oacc[nf][1], inv0, q0v.y));
        *(float2*)&O[oo1] = make_float2(fmaf(oacc[nf][2], inv1, q1v.x),
                                        fmaf(oacc[nf][3], inv1, q1v.y));
    }
}

// ===========================================================================
// LayerNorm (warp per row). EMIT=1 additionally writes bf16 hi/lo split.
// ===========================================================================
template <int EMIT>
__global__ __launch_bounds__(256) void ln_kernel(
    const float* __restrict__ X, const float* __restrict__ gam,
    const float* __restrict__ bet, float* __restrict__ Y,
    __nv_bfloat16* __restrict__ Yh, __nv_bfloat16* __restrict__ Yl)
{
    const int row = blockIdx.x * 8 + (threadIdx.x >> 5);
    const int lane = threadIdx.x & 31;
    const float* x = X + (size_t)row * DM;

    float v[16];
    float sum = 0.f, ss = 0.f;
#pragma unroll
    for (int i = 0; i < 4; ++i) {
        float4 tv = *(const float4*)(x + i * 128 + lane * 4);
        v[i * 4 + 0] = tv.x; v[i * 4 + 1] = tv.y;
        v[i * 4 + 2] = tv.z; v[i * 4 + 3] = tv.w;
        sum += tv.x + tv.y + tv.z + tv.w;
        ss += tv.x * tv.x + tv.y * tv.y + tv.z * tv.z + tv.w * tv.w;
    }
#pragma unroll
    for (int m = 16; m >= 1; m >>= 1) {
        sum += __shfl_xor_sync(0xffffffffu, sum, m);
        ss += __shfl_xor_sync(0xffffffffu, ss, m);
    }
    const float mean = sum * (1.f / DM);
    const float var = ss * (1.f / DM) - mean * mean;
    const float inv = rsqrtf(var + 1e-5f);

    float* y = Y + (size_t)row * DM;
#pragma unroll
    for (int i = 0; i < 4; ++i) {
        const int col = i * 128 + lane * 4;
        float4 gv = *(const float4*)(gam + col);
        float4 bb = *(const float4*)(bet + col);
        float4 o;
        o.x = (v[i * 4 + 0] - mean) * inv * gv.x + bb.x;
        o.y = (v[i * 4 + 1] - mean) * inv * gv.y + bb.y;
        o.z = (v[i * 4 + 2] - mean) * inv * gv.z + bb.z;
        o.w = (v[i * 4 + 3] - mean) * inv * gv.w + bb.w;
        *(float4*)(y + col) = o;
        if (EMIT) {
            uint32_t h0, l0, h1, l1;
            split_pair(o.x, o.y, h0, l0);
            split_pair(o.z, o.w, h1, l1);
            size_t e = (size_t)row * DM + col;
            *(uint2*)&Yh[e] = make_uint2(h0, h1);
            *(uint2*)&Yl[e] = make_uint2(l0, l1);
        }
    }
}

// ===========================================================================
extern "C" void kernel_launch(void* const* d_in, const int* in_sizes, int n_in,
                              void* d_out, int out_size)
{
    const float* Q  = (const float*)d_in[0];
    const float* K  = (const float*)d_in[1];
    const float* Wq = (const float*)d_in[2];
    const float* bq = (const float*)d_in[3];
    const float* Wk = (const float*)d_in[4];
    const float* bk = (const float*)d_in[5];
    const float* Wv = (const float*)d_in[6];
    const float* bv = (const float*)d_in[7];
    const float* Wo = (const float*)d_in[8];
    const float* bo = (const float*)d_in[9];
    const float* g0 = (const float*)d_in[10];
    const float* b0 = (const float*)d_in[11];
    const float* g1 = (const float*)d_in[12];
    const float* b1 = (const float*)d_in[13];
    float* out = (float*)d_out;

    float *Qp, *O, *T, *U;
    __nv_bfloat16 *Ah, *Al, *Kbh, *Kbl, *Qh, *Ql, *Kh, *Kl, *Vh, *Vl, *Wth, *Wtl;
    cudaGetSymbolAddress((void**)&Qp, g_Qp);
    cudaGetSymbolAddress((void**)&O,  g_O);
    cudaGetSymbolAddress((void**)&T,  g_T);
    cudaGetSymbolAddress((void**)&U,  g_U);
    cudaGetSymbolAddress((void**)&Ah, g_Ah);
    cudaGetSymbolAddress((void**)&Al, g_Al);
    cudaGetSymbolAddress((void**)&Kbh, g_Kbh);
    cudaGetSymbolAddress((void**)&Kbl, g_Kbl);
    cudaGetSymbolAddress((void**)&Qh, g_Qh);
    cudaGetSymbolAddress((void**)&Ql, g_Ql);
    cudaGetSymbolAddress((void**)&Kh, g_Kh);
    cudaGetSymbolAddress((void**)&Kl, g_Kl);
    cudaGetSymbolAddress((void**)&Vh, g_Vh);
    cudaGetSymbolAddress((void**)&Vl, g_Vl);
    cudaGetSymbolAddress((void**)&Wth, g_Wth);
    cudaGetSymbolAddress((void**)&Wtl, g_Wtl);

    static int attr_set = 0;
    if (!attr_set) {
        cudaFuncSetAttribute(attn_mma,
            cudaFuncAttributeMaxDynamicSharedMemorySize, A_SMEM);
        cudaFuncSetAttribute(gemm_qkv,
            cudaFuncAttributeMaxDynamicSharedMemorySize, G_SMEM);
        cudaFuncSetAttribute(gemm_mlp,
            cudaFuncAttributeMaxDynamicSharedMemorySize, G_SMEM);
        attr_set = 1;
    }

    const int WSZ = DM * DM;

    // #0: input splits (Q and K fused)
    cvt_split2<<<dim3(512, 2), 256>>>((const float4*)Q, Ah, Al,
                                      (const float4*)K, Kbh, Kbl, TOT / 4);
    // #1: all 4 weight transpose+splits fused
    cvt_wt4<<<dim3(16, 16, 4), dim3(32, 8)>>>(Wq, Wk, Wv, Wo, Wth, Wtl);

    // #2: fused QKV projections (768 CTAs in one grid)
    gemm_qkv<<<dim3(DM / 128, (BT * NQ) / 128, 3), 256, G_SMEM>>>(
        Ah, Al, Kbh, Kbl, Wth, Wtl, bq, bk, bv,
        Qp, Qh, Ql, Kh, Kl, Vh, Vl);

    // #3: attention + Q residual
    attn_mma<<<dim3(NQ / 128, HEADS, BT), 256, A_SMEM>>>(Qp, Qh, Ql, Kh, Kl,
                                                         Vh, Vl, O);

    // #4: LN0 (emit bf16 split of T for the MLP GEMM)
    ln_kernel<1><<<(BT * NQ) / 8, 256>>>(O, g0, b0, T, Ah, Al);

    // #5: U = T + relu(T @ Wo + bo)
    gemm_mlp<<<dim3(DM / 128, (BT * NQ) / 128), 256, G_SMEM>>>(
        Ah, Al, Wth + 3 * WSZ, Wtl + 3 * WSZ, bo, T, U);

    // #6: LN1 -> out
    ln_kernel<0><<<(BT * NQ) / 8, 256>>>(U, g1, b1, out, nullptr, nullptr);
}

// round 12
// speedup vs baseline: 1.1161x; 1.0040x over previous
#include <cuda_runtime.h>
#include <cuda_bf16.h>
#include <math.h>
#include <stdint.h>

#define BT 8
#define NQ 1024
#define DM 512
#define HEADS 8
#define HD 64
#define TOT (BT*NQ*DM)

// fp32 scratch
__device__ float g_O [TOT];
__device__ float g_T [TOT];
__device__ float g_U [TOT];
// bf16 split scratch
__device__ __nv_bfloat16 g_Ah[TOT], g_Al[TOT];     // raw-Q splits, then T splits
__device__ __nv_bfloat16 g_Kbh[TOT], g_Kbl[TOT];   // raw-K splits
__device__ __nv_bfloat16 g_Qh[TOT], g_Ql[TOT];     // projected Q splits
__device__ __nv_bfloat16 g_Kh[TOT], g_Kl[TOT];     // projected K splits
__device__ __nv_bfloat16 g_Vh[TOT], g_Vl[TOT];     // projected V splits
__device__ __nv_bfloat16 g_Wth[4][DM*DM], g_Wtl[4][DM*DM]; // transposed weights

// ===========================================================================
// Helpers
// ===========================================================================
__device__ __forceinline__ uint32_t smem_u32(const void* p) {
    uint32_t a;
    asm("{ .reg .u64 t; cvta.to.shared.u64 t, %1; cvt.u32.u64 %0, t; }"
        : "=r"(a) : "l"(p));
    return a;
}

__device__ __forceinline__ void ldsm4(uint32_t r[4], uint32_t addr) {
    asm volatile("ldmatrix.sync.aligned.m8n8.x4.shared.b16 {%0,%1,%2,%3}, [%4];"
        : "=r"(r[0]), "=r"(r[1]), "=r"(r[2]), "=r"(r[3]) : "r"(addr));
}
__device__ __forceinline__ void ldsm4t(uint32_t r[4], uint32_t addr) {
    asm volatile("ldmatrix.sync.aligned.m8n8.x4.trans.shared.b16 {%0,%1,%2,%3}, [%4];"
        : "=r"(r[0]), "=r"(r[1]), "=r"(r[2]), "=r"(r[3]) : "r"(addr));
}

__device__ __forceinline__ void mma16816(float c[4], const uint32_t a[4],
                                         uint32_t b0, uint32_t b1) {
    asm volatile(
        "mma.sync.aligned.m16n8k16.row.col.f32.bf16.bf16.f32 "
        "{%0,%1,%2,%3}, {%4,%5,%6,%7}, {%8,%9}, {%0,%1,%2,%3};"
        : "+f"(c[0]), "+f"(c[1]), "+f"(c[2]), "+f"(c[3])
        : "r"(a[0]), "r"(a[1]), "r"(a[2]), "r"(a[3]), "r"(b0), "r"(b1));
}

__device__ __forceinline__ uint32_t packbf(float x, float y) {
    __nv_bfloat162 h = __floats2bfloat162_rn(x, y);
    return *reinterpret_cast<uint32_t*>(&h);
}

__device__ __forceinline__ void split_pair(float x, float y,
                                           uint32_t& hi, uint32_t& lo) {
    __nv_bfloat162 h = __floats2bfloat162_rn(x, y);
    float rx = x - __bfloat162float(h.x);
    float ry = y - __bfloat162float(h.y);
    hi = *reinterpret_cast<uint32_t*>(&h);
    lo = packbf(rx, ry);
}

__device__ __forceinline__ void cpa16(uint32_t dst, const void* src) {
    asm volatile("cp.async.ca.shared.global [%0], [%1], 16;"
                 :: "r"(dst), "l"(src));
}
#define CP_COMMIT() asm volatile("cp.async.commit_group;" ::: "memory")
#define CP_WAIT0()  asm volatile("cp.async.wait_group 0;" ::: "memory")
#define CP_WAIT1()  asm volatile("cp.async.wait_group 1;" ::: "memory")

// ===========================================================================
// Fused split-convert: two tensors fp32 -> bf16 hi/lo (blockIdx.y selects)
// ===========================================================================
__global__ __launch_bounds__(256) void cvt_split2(
    const float4* __restrict__ X0, __nv_bfloat16* __restrict__ X0h,
    __nv_bfloat16* __restrict__ X0l,
    const float4* __restrict__ X1, __nv_bfloat16* __restrict__ X1h,
    __nv_bfloat16* __restrict__ X1l, int n4)
{
    const float4* X = blockIdx.y ? X1 : X0;
    __nv_bfloat16* Xh = blockIdx.y ? X1h : X0h;
    __nv_bfloat16* Xl = blockIdx.y ? X1l : X0l;
    for (int i = blockIdx.x * blockDim.x + threadIdx.x; i < n4;
         i += gridDim.x * blockDim.x) {
        float4 v = X[i];
        uint32_t h0, l0, h1, l1;
        split_pair(v.x, v.y, h0, l0);
        split_pair(v.z, v.w, h1, l1);
        *(uint2*)&Xh[4 * i] = make_uint2(h0, h1);
        *(uint2*)&Xl[4 * i] = make_uint2(l0, l1);
    }
}

// Fused weight transpose + split for all 4 weights (blockIdx.z selects)
__global__ __launch_bounds__(256) void cvt_wt4(
    const float* __restrict__ W0, const float* __restrict__ W1,
    const float* __restrict__ W2, const float* __restrict__ W3,
    __nv_bfloat16* __restrict__ WthB, __nv_bfloat16* __restrict__ WtlB)
{
    const float* W = (blockIdx.z == 0) ? W0 : (blockIdx.z == 1) ? W1 :
                     (blockIdx.z == 2) ? W2 : W3;
    __nv_bfloat16* Wth = WthB + (size_t)blockIdx.z * DM * DM;
    __nv_bfloat16* Wtl = WtlB + (size_t)blockIdx.z * DM * DM;

    __shared__ float tile[32][33];
    const int tx = threadIdx.x, ty = threadIdx.y;  // 32 x 8
    const int kb = blockIdx.y * 32, nb = blockIdx.x * 32;
#pragma unroll
    for (int i = 0; i < 32; i += 8)
        tile[ty + i][tx] = W[(size_t)(kb + ty + i) * DM + nb + tx];
    __syncthreads();
#pragma unroll
    for (int i = 0; i < 32; i += 8) {
        float v = tile[tx][ty + i];
        __nv_bfloat16 h = __float2bfloat16(v);
        size_t o = (size_t)(nb + ty + i) * DM + kb + tx;
        Wth[o] = h;
        Wtl[o] = __float2bfloat16(v - __bfloat162float(h));
    }
}

// ===========================================================================
// Shared GEMM mainloop: cp.async 2-stage; j-blocks processed in PAIRS so the
// 24 MMAs of a pair round-robin 8 accumulators (reuse distance 8 issues).
// ===========================================================================
#define GLD 40                 // smem row stride (bf16)
#define GSTG (128 * GLD)       // elems per array per stage
#define G_SMEM (2 * 4 * GSTG * 2)   // bytes = 81920

__device__ __forceinline__ void gemm_mainloop(
    uint32_t base,
    const __nv_bfloat16* __restrict__ Ah, const __nv_bfloat16* __restrict__ Al,
    const __nv_bfloat16* __restrict__ Bh, const __nv_bfloat16* __restrict__ Bl,
    int bm, int bn, int wm, int wn, int lrow, int lhalf,
    int lr0, int ls0, uint32_t o0, uint32_t o1,
    float (&acc)[2][8][4])
{
    // prologue: issue chunk 0
    {
        uint32_t so = base;
        size_t ga0 = (size_t)(bm + lr0) * DM + ls0;
        size_t gb0 = (size_t)(bn + lr0) * DM + ls0;
        cpa16(so + o0, Ah + ga0);            cpa16(so + o1, Ah + ga0 + 8);
        cpa16(so + GSTG*2 + o0, Al + ga0);   cpa16(so + GSTG*2 + o1, Al + ga0 + 8);
        cpa16(so + 2*GSTG*2 + o0, Bh + gb0); cpa16(so + 2*GSTG*2 + o1, Bh + gb0 + 8);
        cpa16(so + 3*GSTG*2 + o0, Bl + gb0); cpa16(so + 3*GSTG*2 + o1, Bl + gb0 + 8);
        CP_COMMIT();
    }

    for (int c = 0; c < 16; ++c) {
        CP_WAIT0();
        __syncthreads();

        const uint32_t uS = base + (c & 1) * (4 * GSTG * 2);
        const uint32_t uAh = uS, uAl = uS + GSTG*2;
        const uint32_t uBh = uS + 2*GSTG*2, uBl = uS + 3*GSTG*2;

        const bool pf = (c + 1 < 16);
        const int k0n = (c + 1) * 32;
        const uint32_t son = base + ((c + 1) & 1) * (4 * GSTG * 2);
        const size_t gan = (size_t)(bm + lr0) * DM + k0n + ls0;
        const size_t gbn = (size_t)(bn + lr0) * DM + k0n + ls0;

#pragma unroll
        for (int kb = 0; kb < 2; ++kb) {
            const uint32_t cofs = (uint32_t)(lhalf + kb * 16) * 2;
            uint32_t ah[2][4], al[2][4];
#pragma unroll
            for (int mf = 0; mf < 2; ++mf) {
                uint32_t rofs = (uint32_t)((wm + mf * 16 + lrow) * GLD) * 2 + cofs;
                ldsm4(ah[mf], uAh + rofs);
                ldsm4(al[mf], uAl + rofs);
            }
#pragma unroll
            for (int jp = 0; jp < 2; ++jp) {
                const int j0 = 2 * jp, j1 = 2 * jp + 1;
                uint32_t bh0[4], bl0[4], bh1[4], bl1[4];
                {
                    uint32_t r0 = (uint32_t)((wn + j0 * 16 + lrow) * GLD) * 2 + cofs;
                    uint32_t r1 = (uint32_t)((wn + j1 * 16 + lrow) * GLD) * 2 + cofs;
                    ldsm4(bh0, uBh + r0);
                    ldsm4(bl0, uBl + r0);
                    ldsm4(bh1, uBh + r1);
                    ldsm4(bl1, uBl + r1);
                }
                // interleave next-chunk cp.async into kb 0's two jp blocks
                if (kb == 0 && pf) {
                    if (jp == 0) {
                        cpa16(son + o0, Ah + gan);
                        cpa16(son + o1, Ah + gan + 8);
                        cpa16(son + GSTG*2 + o0, Al + gan);
                        cpa16(son + GSTG*2 + o1, Al + gan + 8);
                    } else {
                        cpa16(son + 2*GSTG*2 + o0, Bh + gbn);
                        cpa16(son + 2*GSTG*2 + o1, Bh + gbn + 8);
                        cpa16(son + 3*GSTG*2 + o0, Bl + gbn);
                        cpa16(son + 3*GSTG*2 + o1, Bl + gbn + 8);
                        CP_COMMIT();
                    }
                }
                // 24 MMAs over 8 accumulators, reuse distance 8
                // term hh
                mma16816(acc[0][2*j0],   ah[0], bh0[0], bh0[2]);
                mma16816(acc[0][2*j0+1], ah[0], bh0[1], bh0[3]);
                mma16816(acc[0][2*j1],   ah[0], bh1[0], bh1[2]);
                mma16816(acc[0][2*j1+1], ah[0], bh1[1], bh1[3]);
                mma16816(acc[1][2*j0],   ah[1], bh0[0], bh0[2]);
                mma16816(acc[1][2*j0+1], ah[1], bh0[1], bh0[3]);
                mma16816(acc[1][2*j1],   ah[1], bh1[0], bh1[2]);
                mma16816(acc[1][2*j1+1], ah[1], bh1[1], bh1[3]);
                // term hl
                mma16816(acc[0][2*j0],   ah[0], bl0[0], bl0[2]);
                mma16816(acc[0][2*j0+1], ah[0], bl0[1], bl0[3]);
                mma16816(acc[0][2*j1],   ah[0], bl1[0], bl1[2]);
                mma16816(acc[0][2*j1+1], ah[0], bl1[1], bl1[3]);
                mma16816(acc[1][2*j0],   ah[1], bl0[0], bl0[2]);
                mma16816(acc[1][2*j0+1], ah[1], bl0[1], bl0[3]);
                mma16816(acc[1][2*j1],   ah[1], bl1[0], bl1[2]);
                mma16816(acc[1][2*j1+1], ah[1], bl1[1], bl1[3]);
                // term lh
                mma16816(acc[0][2*j0],   al[0], bh0[0], bh0[2]);
                mma16816(acc[0][2*j0+1], al[0], bh0[1], bh0[3]);
                mma16816(acc[0][2*j1],   al[0], bh1[0], bh1[2]);
                mma16816(acc[0][2*j1+1], al[0], bh1[1], bh1[3]);
                mma16816(acc[1][2*j0],   al[1], bh0[0], bh0[2]);
                mma16816(acc[1][2*j0+1], al[1], bh0[1], bh0[3]);
                mma16816(acc[1][2*j1],   al[1], bh1[0], bh1[2]);
                mma16816(acc[1][2*j1+1], al[1], bh1[1], bh1[3]);
            }
        }
    }
}

// ===========================================================================
// Fused QKV projection GEMM: blockIdx.z selects (activation, weight, outputs)
// ===========================================================================
__global__ __launch_bounds__(256, 2) void gemm_qkv(
    const __nv_bfloat16* __restrict__ QAh, const __nv_bfloat16* __restrict__ QAl,
    const __nv_bfloat16* __restrict__ KAh, const __nv_bfloat16* __restrict__ KAl,
    const __nv_bfloat16* __restrict__ WthB, const __nv_bfloat16* __restrict__ WtlB,
    const float* __restrict__ bq, const float* __restrict__ bk,
    const float* __restrict__ bv,
    __nv_bfloat16* __restrict__ Qh, __nv_bfloat16* __restrict__ Ql,
    __nv_bfloat16* __restrict__ Kh, __nv_bfloat16* __restrict__ Kl,
    __nv_bfloat16* __restrict__ Vh, __nv_bfloat16* __restrict__ Vl)
{
    extern __shared__ __nv_bfloat16 gsm[];
    const uint32_t base = smem_u32(gsm);

    const int z = blockIdx.z;
    const __nv_bfloat16* Ah = (z == 0) ? QAh : KAh;
    const __nv_bfloat16* Al = (z == 0) ? QAl : KAl;
    const __nv_bfloat16* Bh = WthB + (size_t)z * DM * DM;
    const __nv_bfloat16* Bl = WtlB + (size_t)z * DM * DM;
    const float* bias = (z == 0) ? bq : (z == 1) ? bk : bv;
    __nv_bfloat16* Ch = (z == 0) ? Qh : (z == 1) ? Kh : Vh;
    __nv_bfloat16* Cl = (z == 0) ? Ql : (z == 1) ? Kl : Vl;

    const int tid = threadIdx.x, wid = tid >> 5, lane = tid & 31;
    const int g = lane >> 2, t = lane & 3;
    const int lrow = lane & 15, lhalf = (lane >> 4) << 3;
    const int bm = blockIdx.y * 128, bn = blockIdx.x * 128;
    const int wm = (wid & 3) * 32, wn = (wid >> 2) * 64;

    const int cid0 = tid * 2;
    const int lr0 = cid0 >> 2, ls0 = (cid0 & 3) * 8;
    const uint32_t o0 = (uint32_t)(lr0 * GLD + ls0) * 2;
    const uint32_t o1 = (uint32_t)(lr0 * GLD + ls0 + 8) * 2;

    float acc[2][8][4] = {};

    gemm_mainloop(base, Ah, Al, Bh, Bl, bm, bn, wm, wn, lrow, lhalf,
                  lr0, ls0, o0, o1, acc);

    // Epilogue
#pragma unroll
    for (int mf = 0; mf < 2; ++mf) {
#pragma unroll
        for (int nf = 0; nf < 8; ++nf) {
            const int row0 = bm + wm + mf * 16 + g;
            const int col = bn + wn + nf * 8 + 2 * t;
            float2 bvv = *(const float2*)&bias[col];
            float v0 = acc[mf][nf][0] + bvv.x, v1 = acc[mf][nf][1] + bvv.y;
            float v2 = acc[mf][nf][2] + bvv.x, v3 = acc[mf][nf][3] + bvv.y;
            size_t q0 = (size_t)row0 * DM + col;
            size_t q1 = (size_t)(row0 + 8) * DM + col;
            uint32_t h, l;
            split_pair(v0, v1, h, l);
            *(uint32_t*)&Ch[q0] = h; *(uint32_t*)&Cl[q0] = l;
            split_pair(v2, v3, h, l);
            *(uint32_t*)&Ch[q1] = h; *(uint32_t*)&Cl[q1] = l;
        }
    }
}

// ===========================================================================
// MLP GEMM: U = R + relu(A @ Wo + bo)
// ===========================================================================
__global__ __launch_bounds__(256, 2) void gemm_mlp(
    const __nv_bfloat16* __restrict__ Ah, const __nv_bfloat16* __restrict__ Al,
    const __nv_bfloat16* __restrict__ Bh, const __nv_bfloat16* __restrict__ Bl,
    const float* __restrict__ bias, const float* __restrict__ R,
    float* __restrict__ C)
{
    extern __shared__ __nv_bfloat16 gsm[];
    const uint32_t base = smem_u32(gsm);

    const int tid = threadIdx.x, wid = tid >> 5, lane = tid & 31;
    const int g = lane >> 2, t = lane & 3;
    const int lrow = lane & 15, lhalf = (lane >> 4) << 3;
    const int bm = blockIdx.y * 128, bn = blockIdx.x * 128;
    const int wm = (wid & 3) * 32, wn = (wid >> 2) * 64;

    const int cid0 = tid * 2;
    const int lr0 = cid0 >> 2, ls0 = (cid0 & 3) * 8;
    const uint32_t o0 = (uint32_t)(lr0 * GLD + ls0) * 2;
    const uint32_t o1 = (uint32_t)(lr0 * GLD + ls0 + 8) * 2;

    float acc[2][8][4] = {};

    gemm_mainloop(base, Ah, Al, Bh, Bl, bm, bn, wm, wn, lrow, lhalf,
                  lr0, ls0, o0, o1, acc);

#pragma unroll
    for (int mf = 0; mf < 2; ++mf) {
#pragma unroll
        for (int nf = 0; nf < 8; ++nf) {
            const int row0 = bm + wm + mf * 16 + g;
            const int col = bn + wn + nf * 8 + 2 * t;
            float2 bvv = *(const float2*)&bias[col];
            float v0 = acc[mf][nf][0] + bvv.x, v1 = acc[mf][nf][1] + bvv.y;
            float v2 = acc[mf][nf][2] + bvv.x, v3 = acc[mf][nf][3] + bvv.y;
            size_t q0 = (size_t)row0 * DM + col;
            size_t q1 = (size_t)(row0 + 8) * DM + col;
            float2 r0 = *(const float2*)&R[q0];
            float2 r1 = *(const float2*)&R[q1];
            v0 = r0.x + fmaxf(v0, 0.f); v1 = r0.y + fmaxf(v1, 0.f);
            v2 = r1.x + fmaxf(v2, 0.f); v3 = r1.y + fmaxf(v3, 0.f);
            *(float2*)&C[q0] = make_float2(v0, v1);
            *(float2*)&C[q1] = make_float2(v2, v3);
        }
    }
}

// ===========================================================================
// Attention: CTA = 128 q-rows x (head, batch); 16 key-chunks of 64,
// cp.async 3-stage; Q frags register-resident; j-PAIR MMA interleaving
// (4 accumulators in flight); sum reductions deferred past the PV loop.
// ===========================================================================
#define ATLD 72
#define ATILE (64 * ATLD)          // elems per 64-row tile
#define ASTG  (4 * ATILE)          // elems per stage (KH,KL,VH,VL)
#define A_SMEM (3 * ASTG * 2)      // 110592 bytes

__global__ __launch_bounds__(256, 2) void attn_mma(
    const __nv_bfloat16* __restrict__ Qh, const __nv_bfloat16* __restrict__ Ql,
    const __nv_bfloat16* __restrict__ Kh, const __nv_bfloat16* __restrict__ Kl,
    const __nv_bfloat16* __restrict__ Vh, const __nv_bfloat16* __restrict__ Vl,
    float* __restrict__ O)
{
    extern __shared__ char sm[];
    const uint32_t sb = smem_u32(sm);
    const int tid = threadIdx.x, wid = tid >> 5, lane = tid & 31;
    const int g = lane >> 2, t = lane & 3;
    const int lrow = lane & 15, lhalf = (lane >> 4) << 3;
    const int b = blockIdx.z, h = blockIdx.y, q0 = blockIdx.x * 128;

    // ---- Q prologue: stage Q tile in smem, pull fragments to registers ----
    for (int idx = tid; idx < 1024; idx += 256) {
        int r = idx >> 3, s8 = (idx & 7) * 8;
        size_t go = ((size_t)(b * NQ) + q0 + r) * DM + h * HD + s8;
        int e = (r * ATLD + s8) * 2;
        *(uint4*)(sm + e) = *(const uint4*)&Qh[go];
        *(uint4*)(sm + 128 * ATLD * 2 + e) = *(const uint4*)&Ql[go];
    }
    __syncthreads();
    uint32_t aqh[4][4], aql[4][4];
#pragma unroll
    for (int kb = 0; kb < 4; ++kb) {
        uint32_t qro = (uint32_t)((wid * 16 + lrow) * ATLD) * 2 +
                       (uint32_t)(lhalf + kb * 16) * 2;
        ldsm4(aqh[kb], sb + qro);
        ldsm4(aql[kb], sb + 128 * ATLD * 2 + qro);
    }
    __syncthreads();   // Q reads done; smem reusable by pipeline

    // load mapping for a 64-row chunk: 512 16B-chunks per tile; 2 per thread
    const int cid0 = tid * 2;
    const int lr0 = cid0 >> 3, ls0 = (cid0 & 7) * 8;
    const uint32_t o0 = (uint32_t)(lr0 * ATLD + ls0) * 2;
    const uint32_t o1 = (uint32_t)(lr0 * ATLD + ls0 + 8) * 2;

    float m0 = -1e30f, m1 = -1e30f, l0 = 0.f, l1 = 0.f;
    float oacc[8][4] = {};

    // prologue: issue chunks 0 and 1
#pragma unroll
    for (int pc = 0; pc < 2; ++pc) {
        uint32_t so = sb + pc * (ASTG * 2);
        size_t go = ((size_t)(b * NQ) + pc * 64 + lr0) * DM + h * HD + ls0;
        cpa16(so + o0, Kh + go);                cpa16(so + o1, Kh + go + 8);
        cpa16(so + ATILE*2 + o0, Kl + go);      cpa16(so + ATILE*2 + o1, Kl + go + 8);
        cpa16(so + 2*ATILE*2 + o0, Vh + go);    cpa16(so + 2*ATILE*2 + o1, Vh + go + 8);
        cpa16(so + 3*ATILE*2 + o0, Vl + go);    cpa16(so + 3*ATILE*2 + o1, Vl + go + 8);
        CP_COMMIT();
    }

    for (int kc = 0; kc < 16; ++kc) {
        if (kc < 15) CP_WAIT1(); else CP_WAIT0();
        __syncthreads();   // chunk kc visible; all warps done with buf (kc+2)%3

        const uint32_t uS = sb + (kc % 3) * (ASTG * 2);
        const uint32_t uKH = uS, uKL = uS + ATILE*2;
        const uint32_t uVH = uS + 2*ATILE*2, uVL = uS + 3*ATILE*2;

        const bool pf = (kc + 2 < 16);
        const uint32_t son = sb + ((kc + 2) % 3) * (ASTG * 2);
        const size_t gon = ((size_t)(b * NQ) + (kc + 2) * 64 + lr0) * DM +
                           h * HD + ls0;

        // ---- S = Q K^T : j-pairs, 12 MMAs over 4 accumulators ----
        float s[8][4];
#pragma unroll
        for (int nf = 0; nf < 8; ++nf)
#pragma unroll
            for (int e = 0; e < 4; ++e) s[nf][e] = 0.f;

#pragma unroll
        for (int kb = 0; kb < 4; ++kb) {
            const uint32_t cofs = (uint32_t)(lhalf + kb * 16) * 2;
#pragma unroll
            for (int jp = 0; jp < 2; ++jp) {
                const int j0 = 2 * jp, j1 = 2 * jp + 1;
                uint32_t kh0[4], kl0[4], kh1[4], kl1[4];
                {
                    uint32_t r0 = (uint32_t)((j0 * 16 + lrow) * ATLD) * 2 + cofs;
                    uint32_t r1 = (uint32_t)((j1 * 16 + lrow) * ATLD) * 2 + cofs;
                    ldsm4(kh0, uKH + r0);
                    ldsm4(kl0, uKL + r0);
                    ldsm4(kh1, uKH + r1);
                    ldsm4(kl1, uKL + r1);
                }
                // interleave next-chunk cp.async into kb 0's two jp blocks
                if (kb == 0 && pf) {
                    if (jp == 0) {
                        cpa16(son + o0, Kh + gon);
                        cpa16(son + o1, Kh + gon + 8);
                        cpa16(son + ATILE*2 + o0, Kl + gon);
                        cpa16(son + ATILE*2 + o1, Kl + gon + 8);
                    } else {
                        cpa16(son + 2*ATILE*2 + o0, Vh + gon);
                        cpa16(son + 2*ATILE*2 + o1, Vh + gon + 8);
                        cpa16(son + 3*ATILE*2 + o0, Vl + gon);
                        cpa16(son + 3*ATILE*2 + o1, Vl + gon + 8);
                        CP_COMMIT();
                    }
                }
                // term hh
                mma16816(s[2*j0],   aqh[kb], kh0[0], kh0[2]);
                mma16816(s[2*j0+1], aqh[kb], kh0[1], kh0[3]);
                mma16816(s[2*j1],   aqh[kb], kh1[0], kh1[2]);
                mma16816(s[2*j1+1], aqh[kb], kh1[1], kh1[3]);
                // term hl
                mma16816(s[2*j0],   aqh[kb], kl0[0], kl0[2]);
                mma16816(s[2*j0+1], aqh[kb], kl0[1], kl0[3]);
                mma16816(s[2*j1],   aqh[kb], kl1[0], kl1[2]);
                mma16816(s[2*j1+1], aqh[kb], kl1[1], kl1[3]);
                // term lh
                mma16816(s[2*j0],   aql[kb], kh0[0], kh0[2]);
                mma16816(s[2*j0+1], aql[kb], kh0[1], kh0[3]);
                mma16816(s[2*j1],   aql[kb], kh1[0], kh1[2]);
                mma16816(s[2*j1+1], aql[kb], kh1[1], kh1[3]);
            }
        }

        // ---- online softmax (rows g and g+8); sums deferred past PV ----
        const float scale = 0.125f;
        float rm0 = -1e30f, rm1 = -1e30f;
#pragma unroll
        for (int nf = 0; nf < 8; ++nf) {
            rm0 = fmaxf(rm0, fmaxf(s[nf][0], s[nf][1]));
            rm1 = fmaxf(rm1, fmaxf(s[nf][2], s[nf][3]));
        }
        rm0 = fmaxf(rm0, __shfl_xor_sync(0xffffffffu, rm0, 1));
        rm0 = fmaxf(rm0, __shfl_xor_sync(0xffffffffu, rm0, 2));
        rm1 = fmaxf(rm1, __shfl_xor_sync(0xffffffffu, rm1, 1));
        rm1 = fmaxf(rm1, __shfl_xor_sync(0xffffffffu, rm1, 2));
        float mn0 = fmaxf(m0, rm0 * scale);
        float mn1 = fmaxf(m1, rm1 * scale);
        float al0 = __expf(m0 - mn0);
        float al1 = __expf(m1 - mn1);
        float sum0 = 0.f, sum1 = 0.f;
#pragma unroll
        for (int nf = 0; nf < 8; ++nf) {
            s[nf][0] = __expf(fmaf(s[nf][0], scale, -mn0));
            s[nf][1] = __expf(fmaf(s[nf][1], scale, -mn0));
            s[nf][2] = __expf(fmaf(s[nf][2], scale, -mn1));
            s[nf][3] = __expf(fmaf(s[nf][3], scale, -mn1));
            sum0 += s[nf][0] + s[nf][1];
            sum1 += s[nf][2] + s[nf][3];
        }
        m0 = mn0; m1 = mn1;
#pragma unroll
        for (int nf = 0; nf < 8; ++nf) {
            oacc[nf][0] *= al0; oacc[nf][1] *= al0;
            oacc[nf][2] *= al1; oacc[nf][3] *= al1;
        }

        // ---- O += P V : per k-slice, j2-pairs, 12 MMAs over 4 accs ----
#pragma unroll
        for (int kb2 = 0; kb2 < 4; ++kb2) {
            uint32_t aph[4], apl[4];
            {
                const float* p0 = s[2 * kb2];
                const float* p1 = s[2 * kb2 + 1];
                split_pair(p0[0], p0[1], aph[0], apl[0]);
                split_pair(p0[2], p0[3], aph[1], apl[1]);
                split_pair(p1[0], p1[1], aph[2], apl[2]);
                split_pair(p1[2], p1[3], aph[3], apl[3]);
            }
#pragma unroll
            for (int jp = 0; jp < 2; ++jp) {
                const int j0 = 2 * jp, j1 = 2 * jp + 1;
                uint32_t vh0[4], vl0[4], vh1[4], vl1[4];
                {
                    uint32_t r0 = (uint32_t)((kb2 * 16 + lrow) * ATLD +
                                             j0 * 16 + lhalf) * 2;
                    uint32_t r1 = (uint32_t)((kb2 * 16 + lrow) * ATLD +
                                             j1 * 16 + lhalf) * 2;
                    ldsm4t(vh0, uVH + r0);
                    ldsm4t(vl0, uVL + r0);
                    ldsm4t(vh1, uVH + r1);
                    ldsm4t(vl1, uVL + r1);
                }
                // term hh
                mma16816(oacc[2*j0],   aph, vh0[0], vh0[1]);
                mma16816(oacc[2*j0+1], aph, vh0[2], vh0[3]);
                mma16816(oacc[2*j1],   aph, vh1[0], vh1[1]);
                mma16816(oacc[2*j1+1], aph, vh1[2], vh1[3]);
                // term hl
                mma16816(oacc[2*j0],   aph, vl0[0], vl0[1]);
                mma16816(oacc[2*j0+1], aph, vl0[2], vl0[3]);
                mma16816(oacc[2*j1],   aph, vl1[0], vl1[1]);
                mma16816(oacc[2*j1+1], aph, vl1[2], vl1[3]);
                // term lh
                mma16816(oacc[2*j0],   apl, vh0[0], vh0[1]);
                mma16816(oacc[2*j0+1], apl, vh0[2], vh0[3]);
                mma16816(oacc[2*j1],   apl, vh1[0], vh1[1]);
                mma16816(oacc[2*j1+1], apl, vh1[2], vh1[3]);
            }
        }

        // deferred sum reductions + l update (off the PV critical path)
        sum0 += __shfl_xor_sync(0xffffffffu, sum0, 1);
        sum0 += __shfl_xor_sync(0xffffffffu, sum0, 2);
        sum1 += __shfl_xor_sync(0xffffffffu, sum1, 1);
        sum1 += __shfl_xor_sync(0xffffffffu, sum1, 2);
        l0 = l0 * al0 + sum0;
        l1 = l1 * al1 + sum1;
    }

    // ---- epilogue: normalize + Q residual (reconstructed from Qh+Ql) ----
    const float inv0 = 1.f / l0, inv1 = 1.f / l1;
    const int r0 = q0 + wid * 16 + g;
#pragma unroll
    for (int nf = 0; nf < 8; ++nf) {
        const int d0 = nf * 8 + 2 * t;
        size_t oo0 = ((size_t)(b * NQ) + r0) * DM + h * HD + d0;
        size_t oo1 = oo0 + (size_t)8 * DM;
        __nv_bfloat162 qh0 = *(const __nv_bfloat162*)&Qh[oo0];
        __nv_bfloat162 ql0 = *(const __nv_bfloat162*)&Ql[oo0];
        __nv_bfloat162 qh1 = *(const __nv_bfloat162*)&Qh[oo1];
        __nv_bfloat162 ql1 = *(const __nv_bfloat162*)&Ql[oo1];
        float qx0 = __bfloat162float(qh0.x) + __bfloat162float(ql0.x);
        float qy0 = __bfloat162float(qh0.y) + __bfloat162float(ql0.y);
        float qx1 = __bfloat162float(qh1.x) + __bfloat162float(ql1.x);
        float qy1 = __bfloat162float(qh1.y) + __bfloat162float(ql1.y);
        *(float2*)&O[oo0] = make_float2(fmaf(oacc[nf][0], inv0, qx0),
                                        fmaf(oacc[nf][1], inv0, qy0));
        *(float2*)&O[oo1] = make_float2(fmaf(oacc[nf][2], inv1, qx1),
                                        fmaf(oacc[nf][3], inv1, qy1));
    }
}

// ===========================================================================
// LayerNorm (warp per row). EMIT=1 additionally writes bf16 hi/lo split.
// ===========================================================================
template <int EMIT>
__global__ __launch_bounds__(256) void ln_kernel(
    const float* __restrict__ X, const float* __restrict__ gam,
    const float* __restrict__ bet, float* __restrict__ Y,
    __nv_bfloat16* __restrict__ Yh, __nv_bfloat16* __restrict__ Yl)
{
    const int row = blockIdx.x * 8 + (threadIdx.x >> 5);
    const int lane = threadIdx.x & 31;
    const float* x = X + (size_t)row * DM;

    float v[16];
    float sum = 0.f, ss = 0.f;
#pragma unroll
    for (int i = 0; i < 4; ++i) {
        float4 tv = *(const float4*)(x + i * 128 + lane * 4);
        v[i * 4 + 0] = tv.x; v[i * 4 + 1] = tv.y;
        v[i * 4 + 2] = tv.z; v[i * 4 + 3] = tv.w;
        sum += tv.x + tv.y + tv.z + tv.w;
        ss += tv.x * tv.x + tv.y * tv.y + tv.z * tv.z + tv.w * tv.w;
    }
#pragma unroll
    for (int m = 16; m >= 1; m >>= 1) {
        sum += __shfl_xor_sync(0xffffffffu, sum, m);
        ss += __shfl_xor_sync(0xffffffffu, ss, m);
    }
    const float mean = sum * (1.f / DM);
    const float var = ss * (1.f / DM) - mean * mean;
    const float inv = rsqrtf(var + 1e-5f);

    float* y = Y + (size_t)row * DM;
#pragma unroll
    for (int i = 0; i < 4; ++i) {
        const int col = i * 128 + lane * 4;
        float4 gv = *(const float4*)(gam + col);
        float4 bb = *(const float4*)(bet + col);
        float4 o;
        o.x = (v[i * 4 + 0] - mean) * inv * gv.x + bb.x;
        o.y = (v[i * 4 + 1] - mean) * inv * gv.y + bb.y;
        o.z = (v[i * 4 + 2] - mean) * inv * gv.z + bb.z;
        o.w = (v[i * 4 + 3] - mean) * inv * gv.w + bb.w;
        *(float4*)(y + col) = o;
        if (EMIT) {
            uint32_t h0, l0, h1, l1;
            split_pair(o.x, o.y, h0, l0);
            split_pair(o.z, o.w, h1, l1);
            size_t e = (size_t)row * DM + col;
            *(uint2*)&Yh[e] = make_uint2(h0, h1);
            *(uint2*)&Yl[e] = make_uint2(l0, l1);
        }
    }
}

// ===========================================================================
extern "C" void kernel_launch(void* const* d_in, const int* in_sizes, int n_in,
                              void* d_out, int out_size)
{
    const float* Q  = (const float*)d_in[0];
    const float* K  = (const float*)d_in[1];
    const float* Wq = (const float*)d_in[2];
    const float* bq = (const float*)d_in[3];
    const float* Wk = (const float*)d_in[4];
    const float* bk = (const float*)d_in[5];
    const float* Wv = (const float*)d_in[6];
    const float* bv = (const float*)d_in[7];
    const float* Wo = (const float*)d_in[8];
    const float* bo = (const float*)d_in[9];
    const float* g0 = (const float*)d_in[10];
    const float* b0 = (const float*)d_in[11];
    const float* g1 = (const float*)d_in[12];
    const float* b1 = (const float*)d_in[13];
    float* out = (float*)d_out;

    float *O, *T, *U;
    __nv_bfloat16 *Ah, *Al, *Kbh, *Kbl, *Qh, *Ql, *Kh, *Kl, *Vh, *Vl, *Wth, *Wtl;
    cudaGetSymbolAddress((void**)&O,  g_O);
    cudaGetSymbolAddress((void**)&T,  g_T);
    cudaGetSymbolAddress((void**)&U,  g_U);
    cudaGetSymbolAddress((void**)&Ah, g_Ah);
    cudaGetSymbolAddress((void**)&Al, g_Al);
    cudaGetSymbolAddress((void**)&Kbh, g_Kbh);
    cudaGetSymbolAddress((void**)&Kbl, g_Kbl);
    cudaGetSymbolAddress((void**)&Qh, g_Qh);
    cudaGetSymbolAddress((void**)&Ql, g_Ql);
    cudaGetSymbolAddress((void**)&Kh, g_Kh);
    cudaGetSymbolAddress((void**)&Kl, g_Kl);
    cudaGetSymbolAddress((void**)&Vh, g_Vh);
    cudaGetSymbolAddress((void**)&Vl, g_Vl);
    cudaGetSymbolAddress((void**)&Wth, g_Wth);
    cudaGetSymbolAddress((void**)&Wtl, g_Wtl);

    static int attr_set = 0;
    if (!attr_set) {
        cudaFuncSetAttribute(attn_mma,
            cudaFuncAttributeMaxDynamicSharedMemorySize, A_SMEM);
        cudaFuncSetAttribute(gemm_qkv,
            cudaFuncAttributeMaxDynamicSharedMemorySize, G_SMEM);
        cudaFuncSetAttribute(gemm_mlp,
            cudaFuncAttributeMaxDynamicSharedMemorySize, G_SMEM);
        attr_set = 1;
    }

    const int WSZ = DM * DM;

    // #0: input splits (Q and K fused)
    cvt_split2<<<dim3(512, 2), 256>>>((const float4*)Q, Ah, Al,
                                      (const float4*)K, Kbh, Kbl, TOT / 4);
    // #1: all 4 weight transpose+splits fused
    cvt_wt4<<<dim3(16, 16, 4), dim3(32, 8)>>>(Wq, Wk, Wv, Wo, Wth, Wtl);

    // #2: fused QKV projections (768 CTAs in one grid)
    gemm_qkv<<<dim3(DM / 128, (BT * NQ) / 128, 3), 256, G_SMEM>>>(
        Ah, Al, Kbh, Kbl, Wth, Wtl, bq, bk, bv,
        Qh, Ql, Kh, Kl, Vh, Vl);

    // #3: attention + Q residual
    attn_mma<<<dim3(NQ / 128, HEADS, BT), 256, A_SMEM>>>(Qh, Ql, Kh, Kl,
                                                         Vh, Vl, O);

    // #4: LN0 (emit bf16 split of T for the MLP GEMM)
    ln_kernel<1><<<(BT * NQ) / 8, 256>>>(O, g0, b0, T, Ah, Al);

    // #5: U = T + relu(T @ Wo + bo)
    gemm_mlp<<<dim3(DM / 128, (BT * NQ) / 128), 256, G_SMEM>>>(
        Ah, Al, Wth + 3 * WSZ, Wtl + 3 * WSZ, bo, T, U);

    // #6: LN1 -> out
    ln_kernel<0><<<(BT * NQ) / 8, 256>>>(U, g1, b1, out, nullptr, nullptr);
}

// round 13
// speedup vs baseline: 1.5524x; 1.3909x over previous
#include <cuda_runtime.h>
#include <cuda_fp16.h>
#include <math.h>
#include <stdint.h>

#define BT 8
#define NQ 1024
#define DM 512
#define HEADS 8
#define HD 64
#define TOT (BT*NQ*DM)

// fp32 scratch
__device__ float g_O [TOT];
__device__ float g_T [TOT];
__device__ float g_U [TOT];
// fp16 split scratch
__device__ __half g_Ah[TOT], g_Al[TOT];     // raw-Q splits, then T splits
__device__ __half g_Kbh[TOT], g_Kbl[TOT];   // raw-K splits
__device__ __half g_Qh[TOT], g_Ql[TOT];     // projected Q (2-term)
__device__ __half g_Kh[TOT];                // projected K (1-term)
__device__ __half g_Vh[TOT], g_Vl[TOT];     // projected V (2-term)
__device__ __half g_Wth[4][DM*DM];          // transposed weights (1-term)

// ===========================================================================
// Helpers
// ===========================================================================
__device__ __forceinline__ uint32_t smem_u32(const void* p) {
    uint32_t a;
    asm("{ .reg .u64 t; cvta.to.shared.u64 t, %1; cvt.u32.u64 %0, t; }"
        : "=r"(a) : "l"(p));
    return a;
}

__device__ __forceinline__ void ldsm4(uint32_t r[4], uint32_t addr) {
    asm volatile("ldmatrix.sync.aligned.m8n8.x4.shared.b16 {%0,%1,%2,%3}, [%4];"
        : "=r"(r[0]), "=r"(r[1]), "=r"(r[2]), "=r"(r[3]) : "r"(addr));
}
__device__ __forceinline__ void ldsm4t(uint32_t r[4], uint32_t addr) {
    asm volatile("ldmatrix.sync.aligned.m8n8.x4.trans.shared.b16 {%0,%1,%2,%3}, [%4];"
        : "=r"(r[0]), "=r"(r[1]), "=r"(r[2]), "=r"(r[3]) : "r"(addr));
}

// f16 x f16 -> f32 MMA
__device__ __forceinline__ void mma16816(float c[4], const uint32_t a[4],
                                         uint32_t b0, uint32_t b1) {
    asm volatile(
        "mma.sync.aligned.m16n8k16.row.col.f32.f16.f16.f32 "
        "{%0,%1,%2,%3}, {%4,%5,%6,%7}, {%8,%9}, {%0,%1,%2,%3};"
        : "+f"(c[0]), "+f"(c[1]), "+f"(c[2]), "+f"(c[3])
        : "r"(a[0]), "r"(a[1]), "r"(a[2]), "r"(a[3]), "r"(b0), "r"(b1));
}

__device__ __forceinline__ uint32_t packh2(float x, float y) {
    __half2 h = __floats2half2_rn(x, y);
    return *reinterpret_cast<uint32_t*>(&h);
}

__device__ __forceinline__ void split_pair_h(float x, float y,
                                             uint32_t& hi, uint32_t& lo) {
    __half2 h = __floats2half2_rn(x, y);
    float rx = x - __half2float(__low2half(h));
    float ry = y - __half2float(__high2half(h));
    hi = *reinterpret_cast<uint32_t*>(&h);
    lo = packh2(rx, ry);
}

__device__ __forceinline__ void cpa16(uint32_t dst, const void* src) {
    asm volatile("cp.async.ca.shared.global [%0], [%1], 16;"
                 :: "r"(dst), "l"(src));
}
#define CP_COMMIT() asm volatile("cp.async.commit_group;" ::: "memory")
#define CP_WAIT0()  asm volatile("cp.async.wait_group 0;" ::: "memory")
#define CP_WAIT1()  asm volatile("cp.async.wait_group 1;" ::: "memory")

// ===========================================================================
// Fused split-convert: two tensors fp32 -> fp16 hi/lo (blockIdx.y selects)
// ===========================================================================
__global__ __launch_bounds__(256) void cvt_split2(
    const float4* __restrict__ X0, __half* __restrict__ X0h,
    __half* __restrict__ X0l,
    const float4* __restrict__ X1, __half* __restrict__ X1h,
    __half* __restrict__ X1l, int n4)
{
    const float4* X = blockIdx.y ? X1 : X0;
    __half* Xh = blockIdx.y ? X1h : X0h;
    __half* Xl = blockIdx.y ? X1l : X0l;
    for (int i = blockIdx.x * blockDim.x + threadIdx.x; i < n4;
         i += gridDim.x * blockDim.x) {
        float4 v = X[i];
        uint32_t h0, l0, h1, l1;
        split_pair_h(v.x, v.y, h0, l0);
        split_pair_h(v.z, v.w, h1, l1);
        *(uint2*)&Xh[4 * i] = make_uint2(h0, h1);
        *(uint2*)&Xl[4 * i] = make_uint2(l0, l1);
    }
}

// Fused weight transpose + fp16 convert (single-term) for all 4 weights
__global__ __launch_bounds__(256) void cvt_wt4(
    const float* __restrict__ W0, const float* __restrict__ W1,
    const float* __restrict__ W2, const float* __restrict__ W3,
    __half* __restrict__ WthB)
{
    const float* W = (blockIdx.z == 0) ? W0 : (blockIdx.z == 1) ? W1 :
                     (blockIdx.z == 2) ? W2 : W3;
    __half* Wth = WthB + (size_t)blockIdx.z * DM * DM;

    __shared__ float tile[32][33];
    const int tx = threadIdx.x, ty = threadIdx.y;  // 32 x 8
    const int kb = blockIdx.y * 32, nb = blockIdx.x * 32;
#pragma unroll
    for (int i = 0; i < 32; i += 8)
        tile[ty + i][tx] = W[(size_t)(kb + ty + i) * DM + nb + tx];
    __syncthreads();
#pragma unroll
    for (int i = 0; i < 32; i += 8) {
        size_t o = (size_t)(nb + ty + i) * DM + kb + tx;
        Wth[o] = __float2half_rn(tile[tx][ty + i]);
    }
}

// ===========================================================================
// Shared GEMM mainloop: cp.async 2-stage; A 2-term fp16, B single fp16.
// Per (kb, j-pair): 16 MMAs over 8 accumulators.
// ===========================================================================
#define GLD 40                 // smem row stride (fp16)
#define GSTG (128 * GLD)       // elems per array per stage
#define G_SMEM (2 * 3 * GSTG * 2)   // bytes = 61440

__device__ __forceinline__ void gemm_mainloop(
    uint32_t base,
    const __half* __restrict__ Ah, const __half* __restrict__ Al,
    const __half* __restrict__ Bh,
    int bm, int bn, int wm, int wn, int lrow, int lhalf,
    int lr0, int ls0, uint32_t o0, uint32_t o1,
    float (&acc)[2][8][4])
{
    // prologue: issue chunk 0
    {
        uint32_t so = base;
        size_t ga0 = (size_t)(bm + lr0) * DM + ls0;
        size_t gb0 = (size_t)(bn + lr0) * DM + ls0;
        cpa16(so + o0, Ah + ga0);            cpa16(so + o1, Ah + ga0 + 8);
        cpa16(so + GSTG*2 + o0, Al + ga0);   cpa16(so + GSTG*2 + o1, Al + ga0 + 8);
        cpa16(so + 2*GSTG*2 + o0, Bh + gb0); cpa16(so + 2*GSTG*2 + o1, Bh + gb0 + 8);
        CP_COMMIT();
    }

    for (int c = 0; c < 16; ++c) {
        CP_WAIT0();
        __syncthreads();

        const uint32_t uS = base + (c & 1) * (3 * GSTG * 2);
        const uint32_t uAh = uS, uAl = uS + GSTG*2;
        const uint32_t uBh = uS + 2*GSTG*2;

        const bool pf = (c + 1 < 16);
        const int k0n = (c + 1) * 32;
        const uint32_t son = base + ((c + 1) & 1) * (3 * GSTG * 2);
        const size_t gan = (size_t)(bm + lr0) * DM + k0n + ls0;
        const size_t gbn = (size_t)(bn + lr0) * DM + k0n + ls0;

#pragma unroll
        for (int kb = 0; kb < 2; ++kb) {
            const uint32_t cofs = (uint32_t)(lhalf + kb * 16) * 2;
            uint32_t ah[2][4], al[2][4];
#pragma unroll
            for (int mf = 0; mf < 2; ++mf) {
                uint32_t rofs = (uint32_t)((wm + mf * 16 + lrow) * GLD) * 2 + cofs;
                ldsm4(ah[mf], uAh + rofs);
                ldsm4(al[mf], uAl + rofs);
            }
#pragma unroll
            for (int jp = 0; jp < 2; ++jp) {
                const int j0 = 2 * jp, j1 = 2 * jp + 1;
                uint32_t bh0[4], bh1[4];
                {
                    uint32_t r0 = (uint32_t)((wn + j0 * 16 + lrow) * GLD) * 2 + cofs;
                    uint32_t r1 = (uint32_t)((wn + j1 * 16 + lrow) * GLD) * 2 + cofs;
                    ldsm4(bh0, uBh + r0);
                    ldsm4(bh1, uBh + r1);
                }
                // interleave next-chunk cp.async into kb 0's two jp blocks
                if (kb == 0 && pf) {
                    if (jp == 0) {
                        cpa16(son + o0, Ah + gan);
                        cpa16(son + o1, Ah + gan + 8);
                        cpa16(son + GSTG*2 + o0, Al + gan);
                        cpa16(son + GSTG*2 + o1, Al + gan + 8);
                    } else {
                        cpa16(son + 2*GSTG*2 + o0, Bh + gbn);
                        cpa16(son + 2*GSTG*2 + o1, Bh + gbn + 8);
                        CP_COMMIT();
                    }
                }
                // 16 MMAs over 8 accumulators
                // term Ah
                mma16816(acc[0][2*j0],   ah[0], bh0[0], bh0[2]);
                mma16816(acc[0][2*j0+1], ah[0], bh0[1], bh0[3]);
                mma16816(acc[0][2*j1],   ah[0], bh1[0], bh1[2]);
                mma16816(acc[0][2*j1+1], ah[0], bh1[1], bh1[3]);
                mma16816(acc[1][2*j0],   ah[1], bh0[0], bh0[2]);
                mma16816(acc[1][2*j0+1], ah[1], bh0[1], bh0[3]);
                mma16816(acc[1][2*j1],   ah[1], bh1[0], bh1[2]);
                mma16816(acc[1][2*j1+1], ah[1], bh1[1], bh1[3]);
                // term Al
                mma16816(acc[0][2*j0],   al[0], bh0[0], bh0[2]);
                mma16816(acc[0][2*j0+1], al[0], bh0[1], bh0[3]);
                mma16816(acc[0][2*j1],   al[0], bh1[0], bh1[2]);
                mma16816(acc[0][2*j1+1], al[0], bh1[1], bh1[3]);
                mma16816(acc[1][2*j0],   al[1], bh0[0], bh0[2]);
                mma16816(acc[1][2*j0+1], al[1], bh0[1], bh0[3]);
                mma16816(acc[1][2*j1],   al[1], bh1[0], bh1[2]);
                mma16816(acc[1][2*j1+1], al[1], bh1[1], bh1[3]);
            }
        }
    }
}

// ===========================================================================
// Fused QKV projection GEMM: blockIdx.z selects (activation, weight, outputs)
//   z=0 -> Qh,Ql (2-term);  z=1 -> Kh (1-term);  z=2 -> Vh,Vl (2-term)
// ===========================================================================
__global__ __launch_bounds__(256, 2) void gemm_qkv(
    const __half* __restrict__ QAh, const __half* __restrict__ QAl,
    const __half* __restrict__ KAh, const __half* __restrict__ KAl,
    const __half* __restrict__ WthB,
    const float* __restrict__ bq, const float* __restrict__ bk,
    const float* __restrict__ bv,
    __half* __restrict__ Qh, __half* __restrict__ Ql,
    __half* __restrict__ Kh,
    __half* __restrict__ Vh, __half* __restrict__ Vl)
{
    extern __shared__ __half gsm[];
    const uint32_t base = smem_u32(gsm);

    const int z = blockIdx.z;
    const __half* Ah = (z == 0) ? QAh : KAh;
    const __half* Al = (z == 0) ? QAl : KAl;
    const __half* Bh = WthB + (size_t)z * DM * DM;
    const float* bias = (z == 0) ? bq : (z == 1) ? bk : bv;
    __half* Ch = (z == 0) ? Qh : (z == 1) ? Kh : Vh;
    __half* Cl = (z == 0) ? Ql : Vl;   // unused when z==1

    const int tid = threadIdx.x, wid = tid >> 5, lane = tid & 31;
    const int g = lane >> 2, t = lane & 3;
    const int lrow = lane & 15, lhalf = (lane >> 4) << 3;
    const int bm = blockIdx.y * 128, bn = blockIdx.x * 128;
    const int wm = (wid & 3) * 32, wn = (wid >> 2) * 64;

    const int cid0 = tid * 2;
    const int lr0 = cid0 >> 2, ls0 = (cid0 & 3) * 8;
    const uint32_t o0 = (uint32_t)(lr0 * GLD + ls0) * 2;
    const uint32_t o1 = (uint32_t)(lr0 * GLD + ls0 + 8) * 2;

    float acc[2][8][4] = {};

    gemm_mainloop(base, Ah, Al, Bh, bm, bn, wm, wn, lrow, lhalf,
                  lr0, ls0, o0, o1, acc);

    // Epilogue
#pragma unroll
    for (int mf = 0; mf < 2; ++mf) {
#pragma unroll
        for (int nf = 0; nf < 8; ++nf) {
            const int row0 = bm + wm + mf * 16 + g;
            const int col = bn + wn + nf * 8 + 2 * t;
            float2 bvv = *(const float2*)&bias[col];
            float v0 = acc[mf][nf][0] + bvv.x, v1 = acc[mf][nf][1] + bvv.y;
            float v2 = acc[mf][nf][2] + bvv.x, v3 = acc[mf][nf][3] + bvv.y;
            size_t q0 = (size_t)row0 * DM + col;
            size_t q1 = (size_t)(row0 + 8) * DM + col;
            if (z == 1) {
                *(uint32_t*)&Ch[q0] = packh2(v0, v1);
                *(uint32_t*)&Ch[q1] = packh2(v2, v3);
            } else {
                uint32_t h, l;
                split_pair_h(v0, v1, h, l);
                *(uint32_t*)&Ch[q0] = h; *(uint32_t*)&Cl[q0] = l;
                split_pair_h(v2, v3, h, l);
                *(uint32_t*)&Ch[q1] = h; *(uint32_t*)&Cl[q1] = l;
            }
        }
    }
}

// ===========================================================================
// MLP GEMM: U = R + relu(A @ Wo + bo)
// ===========================================================================
__global__ __launch_bounds__(256, 2) void gemm_mlp(
    const __half* __restrict__ Ah, const __half* __restrict__ Al,
    const __half* __restrict__ Bh,
    const float* __restrict__ bias, const float* __restrict__ R,
    float* __restrict__ C)
{
    extern __shared__ __half gsm[];
    const uint32_t base = smem_u32(gsm);

    const int tid = threadIdx.x, wid = tid >> 5, lane = tid & 31;
    const int g = lane >> 2, t = lane & 3;
    const int lrow = lane & 15, lhalf = (lane >> 4) << 3;
    const int bm = blockIdx.y * 128, bn = blockIdx.x * 128;
    const int wm = (wid & 3) * 32, wn = (wid >> 2) * 64;

    const int cid0 = tid * 2;
    const int lr0 = cid0 >> 2, ls0 = (cid0 & 3) * 8;
    const uint32_t o0 = (uint32_t)(lr0 * GLD + ls0) * 2;
    const uint32_t o1 = (uint32_t)(lr0 * GLD + ls0 + 8) * 2;

    float acc[2][8][4] = {};

    gemm_mainloop(base, Ah, Al, Bh, bm, bn, wm, wn, lrow, lhalf,
                  lr0, ls0, o0, o1, acc);

#pragma unroll
    for (int mf = 0; mf < 2; ++mf) {
#pragma unroll
        for (int nf = 0; nf < 8; ++nf) {
            const int row0 = bm + wm + mf * 16 + g;
            const int col = bn + wn + nf * 8 + 2 * t;
            float2 bvv = *(const float2*)&bias[col];
            float v0 = acc[mf][nf][0] + bvv.x, v1 = acc[mf][nf][1] + bvv.y;
            float v2 = acc[mf][nf][2] + bvv.x, v3 = acc[mf][nf][3] + bvv.y;
            size_t q0 = (size_t)row0 * DM + col;
            size_t q1 = (size_t)(row0 + 8) * DM + col;
            float2 r0 = *(const float2*)&R[q0];
            float2 r1 = *(const float2*)&R[q1];
            v0 = r0.x + fmaxf(v0, 0.f); v1 = r0.y + fmaxf(v1, 0.f);
            v2 = r1.x + fmaxf(v2, 0.f); v3 = r1.y + fmaxf(v3, 0.f);
            *(float2*)&C[q0] = make_float2(v0, v1);
            *(float2*)&C[q1] = make_float2(v2, v3);
        }
    }
}

// ===========================================================================
// Attention: Q 2-term fp16 (register frags), K single-term, V 2-term.
// S = Qh·Kh + Ql·Kh;  O += Ph·Vh + Ph·Vl  (P single fp16).
// cp.async 3-stage, per-stage tiles: KH, VH, VL.
// ===========================================================================
#define ATLD 72
#define ATILE (64 * ATLD)          // elems per 64-row tile
#define ASTG  (3 * ATILE)          // elems per stage (KH,VH,VL)
#define A_SMEM (3 * ASTG * 2)      // 82944 bytes

__global__ __launch_bounds__(256, 2) void attn_mma(
    const __half* __restrict__ Qh, const __half* __restrict__ Ql,
    const __half* __restrict__ Kh,
    const __half* __restrict__ Vh, const __half* __restrict__ Vl,
    float* __restrict__ O)
{
    extern __shared__ char sm[];
    const uint32_t sb = smem_u32(sm);
    const int tid = threadIdx.x, wid = tid >> 5, lane = tid & 31;
    const int g = lane >> 2, t = lane & 3;
    const int lrow = lane & 15, lhalf = (lane >> 4) << 3;
    const int b = blockIdx.z, h = blockIdx.y, q0 = blockIdx.x * 128;

    // ---- Q prologue: stage Q tile in smem, pull fragments to registers ----
    for (int idx = tid; idx < 1024; idx += 256) {
        int r = idx >> 3, s8 = (idx & 7) * 8;
        size_t go = ((size_t)(b * NQ) + q0 + r) * DM + h * HD + s8;
        int e = (r * ATLD + s8) * 2;
        *(uint4*)(sm + e) = *(const uint4*)&Qh[go];
        *(uint4*)(sm + 128 * ATLD * 2 + e) = *(const uint4*)&Ql[go];
    }
    __syncthreads();
    uint32_t aqh[4][4], aql[4][4];
#pragma unroll
    for (int kb = 0; kb < 4; ++kb) {
        uint32_t qro = (uint32_t)((wid * 16 + lrow) * ATLD) * 2 +
                       (uint32_t)(lhalf + kb * 16) * 2;
        ldsm4(aqh[kb], sb + qro);
        ldsm4(aql[kb], sb + 128 * ATLD * 2 + qro);
    }
    __syncthreads();   // Q reads done; smem reusable by pipeline

    // load mapping for a 64-row chunk: 512 16B-chunks per tile; 2 per thread
    const int cid0 = tid * 2;
    const int lr0 = cid0 >> 3, ls0 = (cid0 & 7) * 8;
    const uint32_t o0 = (uint32_t)(lr0 * ATLD + ls0) * 2;
    const uint32_t o1 = (uint32_t)(lr0 * ATLD + ls0 + 8) * 2;

    float m0 = -1e30f, m1 = -1e30f, l0 = 0.f, l1 = 0.f;
    float oacc[8][4] = {};

    // prologue: issue chunks 0 and 1
#pragma unroll
    for (int pc = 0; pc < 2; ++pc) {
        uint32_t so = sb + pc * (ASTG * 2);
        size_t go = ((size_t)(b * NQ) + pc * 64 + lr0) * DM + h * HD + ls0;
        cpa16(so + o0, Kh + go);                cpa16(so + o1, Kh + go + 8);
        cpa16(so + ATILE*2 + o0, Vh + go);      cpa16(so + ATILE*2 + o1, Vh + go + 8);
        cpa16(so + 2*ATILE*2 + o0, Vl + go);    cpa16(so + 2*ATILE*2 + o1, Vl + go + 8);
        CP_COMMIT();
    }

    for (int kc = 0; kc < 16; ++kc) {
        if (kc < 15) CP_WAIT1(); else CP_WAIT0();
        __syncthreads();   // chunk kc visible; all warps done with buf (kc+2)%3

        const uint32_t uS = sb + (kc % 3) * (ASTG * 2);
        const uint32_t uKH = uS;
        const uint32_t uVH = uS + ATILE*2, uVL = uS + 2*ATILE*2;

        const bool pf = (kc + 2 < 16);
        const uint32_t son = sb + ((kc + 2) % 3) * (ASTG * 2);
        const size_t gon = ((size_t)(b * NQ) + (kc + 2) * 64 + lr0) * DM +
                           h * HD + ls0;

        // ---- S = Q K^T : 2 terms (Qh,Ql) x Kh; j-pairs, 8 MMAs/4 accs ----
        float s[8][4];
#pragma unroll
        for (int nf = 0; nf < 8; ++nf)
#pragma unroll
            for (int e = 0; e < 4; ++e) s[nf][e] = 0.f;

#pragma unroll
        for (int kb = 0; kb < 4; ++kb) {
            const uint32_t cofs = (uint32_t)(lhalf + kb * 16) * 2;
#pragma unroll
            for (int jp = 0; jp < 2; ++jp) {
                const int j0 = 2 * jp, j1 = 2 * jp + 1;
                uint32_t kh0[4], kh1[4];
                {
                    uint32_t r0 = (uint32_t)((j0 * 16 + lrow) * ATLD) * 2 + cofs;
                    uint32_t r1 = (uint32_t)((j1 * 16 + lrow) * ATLD) * 2 + cofs;
                    ldsm4(kh0, uKH + r0);
                    ldsm4(kh1, uKH + r1);
                }
                // interleave next-chunk cp.async into kb 0's two jp blocks
                if (kb == 0 && pf) {
                    if (jp == 0) {
                        cpa16(son + o0, Kh + gon);
                        cpa16(son + o1, Kh + gon + 8);
                        cpa16(son + ATILE*2 + o0, Vh + gon);
                        cpa16(son + ATILE*2 + o1, Vh + gon + 8);
                    } else {
                        cpa16(son + 2*ATILE*2 + o0, Vl + gon);
                        cpa16(son + 2*ATILE*2 + o1, Vl + gon + 8);
                        CP_COMMIT();
                    }
                }
                // term Qh
                mma16816(s[2*j0],   aqh[kb], kh0[0], kh0[2]);
                mma16816(s[2*j0+1], aqh[kb], kh0[1], kh0[3]);
                mma16816(s[2*j1],   aqh[kb], kh1[0], kh1[2]);
                mma16816(s[2*j1+1], aqh[kb], kh1[1], kh1[3]);
                // term Ql
                mma16816(s[2*j0],   aql[kb], kh0[0], kh0[2]);
                mma16816(s[2*j0+1], aql[kb], kh0[1], kh0[3]);
                mma16816(s[2*j1],   aql[kb], kh1[0], kh1[2]);
                mma16816(s[2*j1+1], aql[kb], kh1[1], kh1[3]);
            }
        }

        // ---- online softmax (rows g and g+8); sums deferred past PV ----
        const float scale = 0.125f;
        float rm0 = -1e30f, rm1 = -1e30f;
#pragma unroll
        for (int nf = 0; nf < 8; ++nf) {
            rm0 = fmaxf(rm0, fmaxf(s[nf][0], s[nf][1]));
            rm1 = fmaxf(rm1, fmaxf(s[nf][2], s[nf][3]));
        }
        rm0 = fmaxf(rm0, __shfl_xor_sync(0xffffffffu, rm0, 1));
        rm0 = fmaxf(rm0, __shfl_xor_sync(0xffffffffu, rm0, 2));
        rm1 = fmaxf(rm1, __shfl_xor_sync(0xffffffffu, rm1, 1));
        rm1 = fmaxf(rm1, __shfl_xor_sync(0xffffffffu, rm1, 2));
        float mn0 = fmaxf(m0, rm0 * scale);
        float mn1 = fmaxf(m1, rm1 * scale);
        float al0 = __expf(m0 - mn0);
        float al1 = __expf(m1 - mn1);
        float sum0 = 0.f, sum1 = 0.f;
#pragma unroll
        for (int nf = 0; nf < 8; ++nf) {
            s[nf][0] = __expf(fmaf(s[nf][0], scale, -mn0));
            s[nf][1] = __expf(fmaf(s[nf][1], scale, -mn0));
            s[nf][2] = __expf(fmaf(s[nf][2], scale, -mn1));
            s[nf][3] = __expf(fmaf(s[nf][3], scale, -mn1));
            sum0 += s[nf][0] + s[nf][1];
            sum1 += s[nf][2] + s[nf][3];
        }
        m0 = mn0; m1 = mn1;
#pragma unroll
        for (int nf = 0; nf < 8; ++nf) {
            oacc[nf][0] *= al0; oacc[nf][1] *= al0;
            oacc[nf][2] *= al1; oacc[nf][3] *= al1;
        }

        // ---- O += P V : P single fp16; V 2-term; 8 MMAs/4 accs per jp ----
#pragma unroll
        for (int kb2 = 0; kb2 < 4; ++kb2) {
            uint32_t ph[4];
            {
                const float* p0 = s[2 * kb2];
                const float* p1 = s[2 * kb2 + 1];
                ph[0] = packh2(p0[0], p0[1]);
                ph[1] = packh2(p0[2], p0[3]);
                ph[2] = packh2(p1[0], p1[1]);
                ph[3] = packh2(p1[2], p1[3]);
            }
#pragma unroll
            for (int jp = 0; jp < 2; ++jp) {
                const int j0 = 2 * jp, j1 = 2 * jp + 1;
                uint32_t vh0[4], vl0[4], vh1[4], vl1[4];
                {
                    uint32_t r0 = (uint32_t)((kb2 * 16 + lrow) * ATLD +
                                             j0 * 16 + lhalf) * 2;
                    uint32_t r1 = (uint32_t)((kb2 * 16 + lrow) * ATLD +
                                             j1 * 16 + lhalf) * 2;
                    ldsm4t(vh0, uVH + r0);
                    ldsm4t(vl0, uVL + r0);
                    ldsm4t(vh1, uVH + r1);
                    ldsm4t(vl1, uVL + r1);
                }
                // term Vh
                mma16816(oacc[2*j0],   ph, vh0[0], vh0[1]);
                mma16816(oacc[2*j0+1], ph, vh0[2], vh0[3]);
                mma16816(oacc[2*j1],   ph, vh1[0], vh1[1]);
                mma16816(oacc[2*j1+1], ph, vh1[2], vh1[3]);
                // term Vl
                mma16816(oacc[2*j0],   ph, vl0[0], vl0[1]);
                mma16816(oacc[2*j0+1], ph, vl0[2], vl0[3]);
                mma16816(oacc[2*j1],   ph, vl1[0], vl1[1]);
                mma16816(oacc[2*j1+1], ph, vl1[2], vl1[3]);
            }
        }

        // deferred sum reductions + l update (off the PV critical path)
        sum0 += __shfl_xor_sync(0xffffffffu, sum0, 1);
        sum0 += __shfl_xor_sync(0xffffffffu, sum0, 2);
        sum1 += __shfl_xor_sync(0xffffffffu, sum1, 1);
        sum1 += __shfl_xor_sync(0xffffffffu, sum1, 2);
        l0 = l0 * al0 + sum0;
        l1 = l1 * al1 + sum1;
    }

    // ---- epilogue: normalize + Q residual (reconstructed from Qh+Ql) ----
    const float inv0 = 1.f / l0, inv1 = 1.f / l1;
    const int r0 = q0 + wid * 16 + g;
#pragma unroll
    for (int nf = 0; nf < 8; ++nf) {
        const int d0 = nf * 8 + 2 * t;
        size_t oo0 = ((size_t)(b * NQ) + r0) * DM + h * HD + d0;
        size_t oo1 = oo0 + (size_t)8 * DM;
        __half2 qh0 = *(const __half2*)&Qh[oo0];
        __half2 ql0 = *(const __half2*)&Ql[oo0];
        __half2 qh1 = *(const __half2*)&Qh[oo1];
        __half2 ql1 = *(const __half2*)&Ql[oo1];
        float qx0 = __half2float(__low2half(qh0)) + __half2float(__low2half(ql0));
        float qy0 = __half2float(__high2half(qh0)) + __half2float(__high2half(ql0));
        float qx1 = __half2float(__low2half(qh1)) + __half2float(__low2half(ql1));
        float qy1 = __half2float(__high2half(qh1)) + __half2float(__high2half(ql1));
        *(float2*)&O[oo0] = make_float2(fmaf(oacc[nf][0], inv0, qx0),
                                        fmaf(oacc[nf][1], inv0, qy0));
        *(float2*)&O[oo1] = make_float2(fmaf(oacc[nf][2], inv1, qx1),
                                        fmaf(oacc[nf][3], inv1, qy1));
    }
}

// ===========================================================================
// LayerNorm (warp per row). EMIT=1 additionally writes fp16 hi/lo split.
// ===========================================================================
template <int EMIT>
__global__ __launch_bounds__(256) void ln_kernel(
    const float* __restrict__ X, const float* __restrict__ gam,
    const float* __restrict__ bet, float* __restrict__ Y,
    __half* __restrict__ Yh, __half* __restrict__ Yl)
{
    const int row = blockIdx.x * 8 + (threadIdx.x >> 5);
    const int lane = threadIdx.x & 31;
    const float* x = X + (size_t)row * DM;

    float v[16];
    float sum = 0.f, ss = 0.f;
#pragma unroll
    for (int i = 0; i < 4; ++i) {
        float4 tv = *(const float4*)(x + i * 128 + lane * 4);
        v[i * 4 + 0] = tv.x; v[i * 4 + 1] = tv.y;
        v[i * 4 + 2] = tv.z; v[i * 4 + 3] = tv.w;
        sum += tv.x + tv.y + tv.z + tv.w;
        ss += tv.x * tv.x + tv.y * tv.y + tv.z * tv.z + tv.w * tv.w;
    }
#pragma unroll
    for (int m = 16; m >= 1; m >>= 1) {
        sum += __shfl_xor_sync(0xffffffffu, sum, m);
        ss += __shfl_xor_sync(0xffffffffu, ss, m);
    }
    const float mean = sum * (1.f / DM);
    const float var = ss * (1.f / DM) - mean * mean;
    const float inv = rsqrtf(var + 1e-5f);

    float* y = Y + (size_t)row * DM;
#pragma unroll
    for (int i = 0; i < 4; ++i) {
        const int col = i * 128 + lane * 4;
        float4 gv = *(const float4*)(gam + col);
        float4 bb = *(const float4*)(bet + col);
        float4 o;
        o.x = (v[i * 4 + 0] - mean) * inv * gv.x + bb.x;
        o.y = (v[i * 4 + 1] - mean) * inv * gv.y + bb.y;
        o.z = (v[i * 4 + 2] - mean) * inv * gv.z + bb.z;
        o.w = (v[i * 4 + 3] - mean) * inv * gv.w + bb.w;
        *(float4*)(y + col) = o;
        if (EMIT) {
            uint32_t h0, l0, h1, l1;
            split_pair_h(o.x, o.y, h0, l0);
            split_pair_h(o.z, o.w, h1, l1);
            size_t e = (size_t)row * DM + col;
            *(uint2*)&Yh[e] = make_uint2(h0, h1);
            *(uint2*)&Yl[e] = make_uint2(l0, l1);
        }
    }
}

// ===========================================================================
extern "C" void kernel_launch(void* const* d_in, const int* in_sizes, int n_in,
                              void* d_out, int out_size)
{
    const float* Q  = (const float*)d_in[0];
    const float* K  = (const float*)d_in[1];
    const float* Wq = (const float*)d_in[2];
    const float* bq = (const float*)d_in[3];
    const float* Wk = (const float*)d_in[4];
    const float* bk = (const float*)d_in[5];
    const float* Wv = (const float*)d_in[6];
    const float* bv = (const float*)d_in[7];
    const float* Wo = (const float*)d_in[8];
    const float* bo = (const float*)d_in[9];
    const float* g0 = (const float*)d_in[10];
    const float* b0 = (const float*)d_in[11];
    const float* g1 = (const float*)d_in[12];
    const float* b1 = (const float*)d_in[13];
    float* out = (float*)d_out;

    float *O, *T, *U;
    __half *Ah, *Al, *Kbh, *Kbl, *Qh, *Ql, *Kh, *Vh, *Vl, *Wth;
    cudaGetSymbolAddress((void**)&O,  g_O);
    cudaGetSymbolAddress((void**)&T,  g_T);
    cudaGetSymbolAddress((void**)&U,  g_U);
    cudaGetSymbolAddress((void**)&Ah, g_Ah);
    cudaGetSymbolAddress((void**)&Al, g_Al);
    cudaGetSymbolAddress((void**)&Kbh, g_Kbh);
    cudaGetSymbolAddress((void**)&Kbl, g_Kbl);
    cudaGetSymbolAddress((void**)&Qh, g_Qh);
    cudaGetSymbolAddress((void**)&Ql, g_Ql);
    cudaGetSymbolAddress((void**)&Kh, g_Kh);
    cudaGetSymbolAddress((void**)&Vh, g_Vh);
    cudaGetSymbolAddress((void**)&Vl, g_Vl);
    cudaGetSymbolAddress((void**)&Wth, g_Wth);

    static int attr_set = 0;
    if (!attr_set) {
        cudaFuncSetAttribute(attn_mma,
            cudaFuncAttributeMaxDynamicSharedMemorySize, A_SMEM);
        cudaFuncSetAttribute(gemm_qkv,
            cudaFuncAttributeMaxDynamicSharedMemorySize, G_SMEM);
        cudaFuncSetAttribute(gemm_mlp,
            cudaFuncAttributeMaxDynamicSharedMemorySize, G_SMEM);
        attr_set = 1;
    }

    const int WSZ = DM * DM;

    // #0: input splits (Q and K fused)
    cvt_split2<<<dim3(512, 2), 256>>>((const float4*)Q, Ah, Al,
                                      (const float4*)K, Kbh, Kbl, TOT / 4);
    // #1: all 4 weight transpose+converts fused (single-term fp16)
    cvt_wt4<<<dim3(16, 16, 4), dim3(32, 8)>>>(Wq, Wk, Wv, Wo, Wth);

    // #2: fused QKV projections (768 CTAs in one grid)
    gemm_qkv<<<dim3(DM / 128, (BT * NQ) / 128, 3), 256, G_SMEM>>>(
        Ah, Al, Kbh, Kbl, Wth, bq, bk, bv,
        Qh, Ql, Kh, Vh, Vl);

    // #3: attention + Q residual
    attn_mma<<<dim3(NQ / 128, HEADS, BT), 256, A_SMEM>>>(Qh, Ql, Kh,
                                                         Vh, Vl, O);

    // #4: LN0 (emit fp16 split of T for the MLP GEMM)
    ln_kernel<1><<<(BT * NQ) / 8, 256>>>(O, g0, b0, T, Ah, Al);

    // #5: U = T + relu(T @ Wo + bo)
    gemm_mlp<<<dim3(DM / 128, (BT * NQ) / 128), 256, G_SMEM>>>(
        Ah, Al, Wth + 3 * WSZ, bo, T, U);

    // #6: LN1 -> out
    ln_kernel<0><<<(BT * NQ) / 8, 256>>>(U, g1, b1, out, nullptr, nullptr);
}